// round 8
// baseline (speedup 1.0000x reference)
#include <cuda_runtime.h>
#include <math.h>

// Problem constants
#define D_  768
#define H_  12
#define E_  64
#define S_  2000
#define MQ  2048    // B*L*TQ
#define BLn 256     // B*L
#define TQn 8
#define NSPLIT 3

// Scratch (device globals: allocation-free)
__device__ unsigned g_Xq[MQ * D_];            // tf32 bits (LN output)
__device__ unsigned g_Xk[S_ * D_];
__device__ unsigned g_Xv[S_ * D_];
__device__ unsigned g_Wt[4 * D_ * D_];        // tf32 weights: Wq,Wk,Wv,Wo
__device__ float g_Qb[MQ * D_];
__device__ float g_Kb[S_ * D_];
__device__ float g_Vb[S_ * D_];
__device__ float g_Oacc[NSPLIT * MQ * D_];    // unnormalized per-split attn out
__device__ float g_ML[NSPLIT * MQ * H_ * 2];  // per-split (m, l)
__device__ unsigned g_Pool[BLn * D_];         // tf32 bits (feeds out-proj)

// ---------------------------------------------------------------------------
// helpers
// ---------------------------------------------------------------------------
__device__ __forceinline__ unsigned f2tf(float x) {
    unsigned r;
    asm("cvt.rna.tf32.f32 %0, %1;" : "=r"(r) : "f"(x));
    return r;
}

__device__ __forceinline__ void mma_tf32(float* d, const unsigned* a,
                                         unsigned b0, unsigned b1) {
    asm volatile(
        "mma.sync.aligned.m16n8k8.row.col.f32.tf32.tf32.f32 "
        "{%0,%1,%2,%3},{%4,%5,%6,%7},{%8,%9},{%0,%1,%2,%3};\n"
        : "+f"(d[0]), "+f"(d[1]), "+f"(d[2]), "+f"(d[3])
        : "r"(a[0]), "r"(a[1]), "r"(a[2]), "r"(a[3]), "r"(b0), "r"(b1));
}

__device__ __forceinline__ void cp16(unsigned* dst_smem, const void* src, bool valid) {
    unsigned daddr = (unsigned)__cvta_generic_to_shared(dst_smem);
    int sz = valid ? 16 : 0;
    asm volatile("cp.async.cg.shared.global [%0], [%1], 16, %2;\n"
                 :: "r"(daddr), "l"(src), "r"(sz));
}
__device__ __forceinline__ void cp_commit() {
    asm volatile("cp.async.commit_group;\n");
}
template <int N>
__device__ __forceinline__ void cp_wait() {
    asm volatile("cp.async.wait_group %0;\n" :: "n"(N));
}

// ---------------------------------------------------------------------------
// Weight conversion to tf32 bits: 4 matrices of D_*D_
// ---------------------------------------------------------------------------
__global__ void conv_w_kernel(const float* W0, const float* W1,
                              const float* W2, const float* W3,
                              unsigned* dst) {
    int z = blockIdx.y;
    const float* s = (z == 0) ? W0 : (z == 1) ? W1 : (z == 2) ? W2 : W3;
    int i = blockIdx.x * 256 + threadIdx.x;
    if (i < D_ * D_) dst[(size_t)z * D_ * D_ + i] = f2tf(s[i]);
}

// ---------------------------------------------------------------------------
// LayerNorm: one block per row of 768, 256 threads; writes tf32 bits
// ---------------------------------------------------------------------------
__global__ void ln_kernel(const float* __restrict__ x, unsigned* __restrict__ y,
                          const float* __restrict__ g, const float* __restrict__ b) {
    int row = blockIdx.x;
    const float* xr = x + (size_t)row * D_;
    int t = threadIdx.x;
    float v0 = xr[t], v1 = xr[t + 256], v2 = xr[t + 512];
    float s  = v0 + v1 + v2;
    float ss = v0 * v0 + v1 * v1 + v2 * v2;

    __shared__ float redS[8], redQ[8];
    #pragma unroll
    for (int o = 16; o > 0; o >>= 1) {
        s  += __shfl_xor_sync(0xffffffffu, s, o);
        ss += __shfl_xor_sync(0xffffffffu, ss, o);
    }
    int warp = t >> 5, lane = t & 31;
    if (lane == 0) { redS[warp] = s; redQ[warp] = ss; }
    __syncthreads();
    float sum = 0.f, sq = 0.f;
    #pragma unroll
    for (int w = 0; w < 8; w++) { sum += redS[w]; sq += redQ[w]; }

    float mean = sum * (1.0f / D_);
    float var  = sq * (1.0f / D_) - mean * mean;
    float rs   = rsqrtf(var + 1e-5f);

    unsigned* yr = y + (size_t)row * D_;
    yr[t]       = f2tf((v0 - mean) * rs * g[t]       + b[t]);
    yr[t + 256] = f2tf((v1 - mean) * rs * g[t + 256] + b[t + 256]);
    yr[t + 512] = f2tf((v2 - mean) * rs * g[t + 512] + b[t + 512]);
}

// ---------------------------------------------------------------------------
// Batched TF32 GEMM v2: cp.async double-buffered pipeline.
// Operands A, W are PRE-CONVERTED tf32 bits in global.
// CTA 128x128, BK=32, 256 threads, warp tile 64x32. Dyn smem 73.7KB, occ 2.
// Staging coverage: 2 threads per row; each thread stages 4 contiguous quads
// (16 words) of A and W -> full 128x32 tiles.
// ---------------------------------------------------------------------------
#define GSM (128 * 36)
#define GEMM_SMEM (2 * 2 * GSM * 4)
#define NKT (D_ / 32)          /* 24 k-tiles */

__global__ __launch_bounds__(256, 2)
void gemm3_tf32(const unsigned* A0, const unsigned* W0, const float* bi0, float* C0, int M0,
                const unsigned* A1, const unsigned* W1, const float* bi1, float* C1, int M1,
                const unsigned* A2, const unsigned* W2, const float* bi2, float* C2, int M2) {
    const unsigned* A; const unsigned* W; const float* bias; float* C; int M;
    if (blockIdx.z == 0) { A = A0; W = W0; bias = bi0; C = C0; M = M0; }
    else if (blockIdx.z == 1) { A = A1; W = W1; bias = bi1; C = C1; M = M1; }
    else { A = A2; W = W2; bias = bi2; C = C2; M = M2; }

    extern __shared__ unsigned smg[];   // [2][As GSM | Ws GSM]

    int t = threadIdx.x, w = t >> 5, lane = t & 31;
    int g = lane >> 2, c = lane & 3;
    int wm = w >> 2, wn = w & 3;
    int row0 = blockIdx.y * 128;
    int col0 = blockIdx.x * 128;

    // staging: 2 threads per row; each thread covers 16 consecutive k-words
    int sr = t >> 1;                 // row 0..127
    int sk = (t & 1) << 4;           // 0 or 16
    auto stage = [&](int kt, int buf) {
        unsigned* As = smg + buf * 2 * GSM;
        unsigned* Ws = As + GSM;
        int k0 = kt * 32;
        int ar = row0 + sr;
        bool av = ar < M;
        const unsigned* asrc = A + (size_t)ar * D_ + k0 + sk;
        const unsigned* wsrc = W + (size_t)(col0 + sr) * D_ + k0 + sk;
        #pragma unroll
        for (int q = 0; q < 4; q++) {
            int kq = sk + q * 4;
            cp16(&As[sr * 36 + kq], asrc + q * 4, av);
            cp16(&Ws[sr * 36 + kq], wsrc + q * 4, true);
        }
    };

    float acc[4][4][4];
    #pragma unroll
    for (int i = 0; i < 4; i++)
        #pragma unroll
        for (int j = 0; j < 4; j++)
            #pragma unroll
            for (int k = 0; k < 4; k++) acc[i][j][k] = 0.f;

    stage(0, 0);
    cp_commit();

    for (int kt = 0; kt < NKT; kt++) {
        if (kt + 1 < NKT) {
            stage(kt + 1, (kt + 1) & 1);
            cp_commit();
            cp_wait<1>();
        } else {
            cp_wait<0>();
        }
        __syncthreads();

        const unsigned* As = smg + (kt & 1) * 2 * GSM;
        const unsigned* Ws = As + GSM;

        #pragma unroll
        for (int ks = 0; ks < 4; ks++) {
            int kk = ks * 8;
            unsigned a[4][4];
            #pragma unroll
            for (int mt = 0; mt < 4; mt++) {
                int base = wm * 64 + mt * 16;
                a[mt][0] = As[(base + g)     * 36 + kk + c];
                a[mt][1] = As[(base + g + 8) * 36 + kk + c];
                a[mt][2] = As[(base + g)     * 36 + kk + 4 + c];
                a[mt][3] = As[(base + g + 8) * 36 + kk + 4 + c];
            }
            #pragma unroll
            for (int nt = 0; nt < 4; nt++) {
                int n = wn * 32 + nt * 8 + g;
                unsigned b0 = Ws[n * 36 + kk + c];
                unsigned b1 = Ws[n * 36 + kk + 4 + c];
                #pragma unroll
                for (int mt = 0; mt < 4; mt++)
                    mma_tf32(acc[mt][nt], a[mt], b0, b1);
            }
        }
        __syncthreads();
    }

    #pragma unroll
    for (int mt = 0; mt < 4; mt++) {
        int rA = row0 + wm * 64 + mt * 16 + g;
        int rB = rA + 8;
        #pragma unroll
        for (int nt = 0; nt < 4; nt++) {
            int colb = col0 + wn * 32 + nt * 8 + 2 * c;
            float b0v = bias[colb], b1v = bias[colb + 1];
            if (rA < M) {
                C[(size_t)rA * D_ + colb]     = acc[mt][nt][0] + b0v;
                C[(size_t)rA * D_ + colb + 1] = acc[mt][nt][1] + b1v;
            }
            if (rB < M) {
                C[(size_t)rB * D_ + colb]     = acc[mt][nt][2] + b0v;
                C[(size_t)rB * D_ + colb + 1] = acc[mt][nt][3] + b1v;
            }
        }
    }
}

// ---------------------------------------------------------------------------
// TF32 flash attention v3 (R6 verbatim): register-P PV via permuted K,
// ASC=32, occ 2, split-KV x3. grid (8,12,3) = 288 CTAs, one wave.
// ---------------------------------------------------------------------------
#define AQT 256
#define ASC 32
#define NCH ((S_ + ASC - 1) / ASC)              /* 63 */
#define CHSPLIT ((NCH + NSPLIT - 1) / NSPLIT)   /* 21 */
#define ATTN_WORDS (AQT*68 + ASC*68 + ASC*72 + ASC)
#define ATTN_SMEM  (ATTN_WORDS * 4)

__global__ __launch_bounds__(256, 2)
void attn_tf32(const float* __restrict__ Q, const float* __restrict__ K,
               const float* __restrict__ V, const int* __restrict__ mask,
               float* __restrict__ Oacc, float* __restrict__ ML) {
    extern __shared__ unsigned smu[];
    unsigned* Qs = smu;                      // [256][68]
    unsigned* Ks = Qs + AQT * 68;            // [32][68]
    unsigned* Vs = Ks + ASC * 68;            // [32][72] rows permuted
    float* maskAdd = (float*)(Vs + ASC * 72);// [32]

    int h = blockIdx.y;
    int z = blockIdx.z;
    int row0 = blockIdx.x * AQT;
    int t = threadIdx.x, w = t >> 5, lane = t & 31;
    int g = lane >> 2, c = lane & 3;
    int wrow = w * 32;

    // load Q tile (tf32)
    #pragma unroll 4
    for (int i = t; i < AQT * 16; i += 256) {
        int r = i >> 4, e4 = (i & 15) << 2;
        float4 q4 = *(const float4*)(Q + (size_t)(row0 + r) * D_ + h * E_ + e4);
        uint4 u = make_uint4(f2tf(q4.x), f2tf(q4.y), f2tf(q4.z), f2tf(q4.w));
        *(uint4*)&Qs[r * 68 + e4] = u;
    }

    float mA[2] = {-1e30f, -1e30f}, mB[2] = {-1e30f, -1e30f};
    float lA[2] = {0.f, 0.f}, lB[2] = {0.f, 0.f};
    float acc[2][8][4];
    #pragma unroll
    for (int mt = 0; mt < 2; mt++)
        #pragma unroll
        for (int nt = 0; nt < 8; nt++)
            #pragma unroll
            for (int k = 0; k < 4; k++) acc[mt][nt][k] = 0.f;

    int chBeg = z * CHSPLIT;
    int chEnd = min(chBeg + CHSPLIT, NCH);
    for (int ch = chBeg; ch < chEnd; ch++) {
        int s0 = ch * ASC;
        __syncthreads();

        // stage K (natural rows) and V (permuted rows); zero tail
        #pragma unroll 2
        for (int i = t; i < ASC * 16; i += 256) {
            int s = i >> 4, e4 = (i & 15) << 2;
            int gs = s0 + s;
            float4 kv = make_float4(0.f, 0.f, 0.f, 0.f);
            float4 vv = make_float4(0.f, 0.f, 0.f, 0.f);
            if (gs < S_) {
                kv = *(const float4*)(K + (size_t)gs * D_ + h * E_ + e4);
                vv = *(const float4*)(V + (size_t)gs * D_ + h * E_ + e4);
            }
            *(uint4*)&Ks[s * 68 + e4] = make_uint4(f2tf(kv.x), f2tf(kv.y), f2tf(kv.z), f2tf(kv.w));
            int sw = s & 7;
            int sp = (s & ~7) | ((sw & 1) ? 4 + (sw >> 1) : (sw >> 1));
            *(uint4*)&Vs[sp * 72 + e4] = make_uint4(f2tf(vv.x), f2tf(vv.y), f2tf(vv.z), f2tf(vv.w));
        }
        if (t < ASC) {
            int gs = s0 + t;
            maskAdd[t] = (gs < S_ && mask[gs] != 0) ? 0.f : -1e30f;
        }
        __syncthreads();

        // ---- scores = Q @ K^T  (32 cols) ----
        float sc[2][4][4];
        #pragma unroll
        for (int mt = 0; mt < 2; mt++)
            #pragma unroll
            for (int nt = 0; nt < 4; nt++)
                #pragma unroll
                for (int k = 0; k < 4; k++) sc[mt][nt][k] = 0.f;

        #pragma unroll
        for (int ks = 0; ks < 8; ks++) {
            int k0 = ks * 8;
            unsigned a[2][4];
            #pragma unroll
            for (int mt = 0; mt < 2; mt++) {
                int base = wrow + mt * 16;
                a[mt][0] = Qs[(base + g)     * 68 + k0 + c];
                a[mt][1] = Qs[(base + g + 8) * 68 + k0 + c];
                a[mt][2] = Qs[(base + g)     * 68 + k0 + 4 + c];
                a[mt][3] = Qs[(base + g + 8) * 68 + k0 + 4 + c];
            }
            #pragma unroll
            for (int nt = 0; nt < 4; nt++) {
                int n0 = nt * 8;
                unsigned b0 = Ks[(n0 + g) * 68 + k0 + c];
                unsigned b1 = Ks[(n0 + g) * 68 + k0 + 4 + c];
                mma_tf32(sc[0][nt], a[0], b0, b1);
                mma_tf32(sc[1][nt], a[1], b0, b1);
            }
        }

        // ---- online softmax; exp'd P stays in registers ----
        #pragma unroll
        for (int mt = 0; mt < 2; mt++) {
            float mxA = -1e30f, mxB = -1e30f;
            #pragma unroll
            for (int nt = 0; nt < 4; nt++) {
                int j0 = nt * 8 + 2 * c;
                float ma0 = maskAdd[j0], ma1 = maskAdd[j0 + 1];
                sc[mt][nt][0] = sc[mt][nt][0] * 0.125f + ma0;
                sc[mt][nt][1] = sc[mt][nt][1] * 0.125f + ma1;
                sc[mt][nt][2] = sc[mt][nt][2] * 0.125f + ma0;
                sc[mt][nt][3] = sc[mt][nt][3] * 0.125f + ma1;
                mxA = fmaxf(mxA, fmaxf(sc[mt][nt][0], sc[mt][nt][1]));
                mxB = fmaxf(mxB, fmaxf(sc[mt][nt][2], sc[mt][nt][3]));
            }
            mxA = fmaxf(mxA, __shfl_xor_sync(0xffffffffu, mxA, 1));
            mxA = fmaxf(mxA, __shfl_xor_sync(0xffffffffu, mxA, 2));
            mxB = fmaxf(mxB, __shfl_xor_sync(0xffffffffu, mxB, 1));
            mxB = fmaxf(mxB, __shfl_xor_sync(0xffffffffu, mxB, 2));

            float mnA = fmaxf(mA[mt], mxA);
            float mnB = fmaxf(mB[mt], mxB);
            float corrA = __expf(mA[mt] - mnA);
            float corrB = __expf(mB[mt] - mnB);
            mA[mt] = mnA; mB[mt] = mnB;

            float psA = 0.f, psB = 0.f;
            #pragma unroll
            for (int nt = 0; nt < 4; nt++) {
                float p0 = __expf(sc[mt][nt][0] - mnA);
                float p1 = __expf(sc[mt][nt][1] - mnA);
                float p2 = __expf(sc[mt][nt][2] - mnB);
                float p3 = __expf(sc[mt][nt][3] - mnB);
                psA += p0 + p1; psB += p2 + p3;
                sc[mt][nt][0] = __uint_as_float(f2tf(p0));
                sc[mt][nt][1] = __uint_as_float(f2tf(p1));
                sc[mt][nt][2] = __uint_as_float(f2tf(p2));
                sc[mt][nt][3] = __uint_as_float(f2tf(p3));
            }
            psA += __shfl_xor_sync(0xffffffffu, psA, 1);
            psA += __shfl_xor_sync(0xffffffffu, psA, 2);
            psB += __shfl_xor_sync(0xffffffffu, psB, 1);
            psB += __shfl_xor_sync(0xffffffffu, psB, 2);
            lA[mt] = lA[mt] * corrA + psA;
            lB[mt] = lB[mt] * corrB + psB;
            #pragma unroll
            for (int nt = 0; nt < 8; nt++) {
                acc[mt][nt][0] *= corrA; acc[mt][nt][1] *= corrA;
                acc[mt][nt][2] *= corrB; acc[mt][nt][3] *= corrB;
            }
        }

        // ---- acc += P @ V (register A-operands, permuted-K V) ----
        #pragma unroll
        for (int ks = 0; ks < 4; ks++) {
            int k0 = ks * 8;
            unsigned aP[2][4];
            #pragma unroll
            for (int mt = 0; mt < 2; mt++) {
                aP[mt][0] = __float_as_uint(sc[mt][ks][0]);
                aP[mt][1] = __float_as_uint(sc[mt][ks][2]);
                aP[mt][2] = __float_as_uint(sc[mt][ks][1]);
                aP[mt][3] = __float_as_uint(sc[mt][ks][3]);
            }
            #pragma unroll
            for (int nt = 0; nt < 8; nt++) {
                int e0 = nt * 8;
                unsigned b0 = Vs[(k0 + c)     * 72 + e0 + g];
                unsigned b1 = Vs[(k0 + 4 + c) * 72 + e0 + g];
                mma_tf32(acc[0][nt], aP[0], b0, b1);
                mma_tf32(acc[1][nt], aP[1], b0, b1);
            }
        }
    }

    // epilogue: store unnormalized acc + (m,l)
    #pragma unroll
    for (int mt = 0; mt < 2; mt++) {
        int rA = row0 + wrow + mt * 16 + g;
        int rB = rA + 8;
        float* obase = Oacc + (size_t)z * MQ * D_;
        #pragma unroll
        for (int nt = 0; nt < 8; nt++) {
            int col = h * E_ + nt * 8 + 2 * c;
            *(float2*)&obase[(size_t)rA * D_ + col] =
                make_float2(acc[mt][nt][0], acc[mt][nt][1]);
            *(float2*)&obase[(size_t)rB * D_ + col] =
                make_float2(acc[mt][nt][2], acc[mt][nt][3]);
        }
        if (c == 0) {
            size_t iA = ((size_t)(z * MQ + rA) * H_ + h) * 2;
            size_t iB = ((size_t)(z * MQ + rB) * H_ + h) * 2;
            ML[iA]     = mA[mt]; ML[iA + 1] = lA[mt];
            ML[iB]     = mB[mt]; ML[iB + 1] = lB[mt];
        }
    }
}

// ---------------------------------------------------------------------------
// Split-KV combine + mean-pool over TQ=8; writes tf32 bits (feeds out-proj)
// ---------------------------------------------------------------------------
__global__ void combine_pool_kernel(const float* __restrict__ Oacc,
                                    const float* __restrict__ ML,
                                    unsigned* __restrict__ P) {
    int idx = blockIdx.x * 256 + threadIdx.x;
    if (idx >= BLn * D_) return;
    int bl = idx / D_, d = idx % D_;
    int h = d >> 6;
    float s = 0.f;
    #pragma unroll
    for (int tq = 0; tq < TQn; tq++) {
        int row = bl * TQn + tq;
        size_t i0 = ((size_t)(0 * MQ + row) * H_ + h) * 2;
        size_t i1 = ((size_t)(1 * MQ + row) * H_ + h) * 2;
        size_t i2 = ((size_t)(2 * MQ + row) * H_ + h) * 2;
        float m0 = ML[i0], l0 = ML[i0 + 1];
        float m1 = ML[i1], l1 = ML[i1 + 1];
        float m2 = ML[i2], l2 = ML[i2 + 1];
        float M = fmaxf(m0, fmaxf(m1, m2));
        float w0 = __expf(m0 - M), w1 = __expf(m1 - M), w2 = __expf(m2 - M);
        float denom = l0 * w0 + l1 * w1 + l2 * w2;
        float a0 = Oacc[(size_t)(0 * MQ + row) * D_ + d];
        float a1 = Oacc[(size_t)(1 * MQ + row) * D_ + d];
        float a2 = Oacc[(size_t)(2 * MQ + row) * D_ + d];
        s += (a0 * w0 + a1 * w1 + a2 * w2) / denom;
    }
    P[idx] = f2tf(s * (1.0f / TQn));
}

// ---------------------------------------------------------------------------
extern "C" void kernel_launch(void* const* d_in, const int* in_sizes, int n_in,
                              void* d_out, int out_size) {
    const float* target     = (const float*)d_in[0];
    const float* key_bank   = (const float*)d_in[1];
    const float* value_bank = (const float*)d_in[2];
    const int*   bank_mask  = (const int*)  d_in[3];
    const float* Wq = (const float*)d_in[4];
    const float* bq = (const float*)d_in[5];
    const float* Wk = (const float*)d_in[6];
    const float* bk = (const float*)d_in[7];
    const float* Wv = (const float*)d_in[8];
    const float* bv = (const float*)d_in[9];
    const float* Wo = (const float*)d_in[10];
    const float* bo = (const float*)d_in[11];
    const float* gq = (const float*)d_in[12];
    const float* betaq = (const float*)d_in[13];
    const float* gkv = (const float*)d_in[14];
    const float* betakv = (const float*)d_in[15];
    float* out = (float*)d_out;

    unsigned *Xq, *Xk, *Xv, *Wt, *Pool;
    float *Qb, *Kb, *Vb, *Oacc, *ML;
    cudaGetSymbolAddress((void**)&Xq,  g_Xq);
    cudaGetSymbolAddress((void**)&Xk,  g_Xk);
    cudaGetSymbolAddress((void**)&Xv,  g_Xv);
    cudaGetSymbolAddress((void**)&Wt,  g_Wt);
    cudaGetSymbolAddress((void**)&Qb,  g_Qb);
    cudaGetSymbolAddress((void**)&Kb,  g_Kb);
    cudaGetSymbolAddress((void**)&Vb,  g_Vb);
    cudaGetSymbolAddress((void**)&Oacc, g_Oacc);
    cudaGetSymbolAddress((void**)&ML,  g_ML);
    cudaGetSymbolAddress((void**)&Pool, g_Pool);

    cudaFuncSetAttribute(attn_tf32,
                         cudaFuncAttributeMaxDynamicSharedMemorySize, ATTN_SMEM);
    cudaFuncSetAttribute(gemm3_tf32,
                         cudaFuncAttributeMaxDynamicSharedMemorySize, GEMM_SMEM);

    // 0. Convert weights to tf32 bits
    conv_w_kernel<<<dim3((D_ * D_ + 255) / 256, 4), 256>>>(Wq, Wk, Wv, Wo, Wt);

    // 1. LayerNorms (write tf32 bits)
    ln_kernel<<<MQ, 256>>>(target, Xq, gq, betaq);
    ln_kernel<<<S_, 256>>>(key_bank, Xk, gkv, betakv);
    ln_kernel<<<S_, 256>>>(value_bank, Xv, gkv, betakv);

    // 2. Q/K/V projections: cp.async pipelined batched GEMM (288 CTAs)
    gemm3_tf32<<<dim3(D_ / 128, 16, 3), 256, GEMM_SMEM>>>(
        Xq, Wt + 0 * D_ * D_, bq, Qb, MQ,
        Xk, Wt + 1 * D_ * D_, bk, Kb, S_,
        Xv, Wt + 2 * D_ * D_, bv, Vb, S_);

    // 3. Attention: split-KV x3, occ 2 => 288 CTAs in ONE wave
    attn_tf32<<<dim3(MQ / AQT, H_, NSPLIT), 256, ATTN_SMEM>>>(
        Qb, Kb, Vb, bank_mask, Oacc, ML);

    // 4. Combine splits + mean-pool over TQ (writes tf32 bits)
    combine_pool_kernel<<<(BLn * D_ + 255) / 256, 256>>>(Oacc, ML, Pool);

    // 5. Output projection
    gemm3_tf32<<<dim3(D_ / 128, 2, 1), 256, GEMM_SMEM>>>(
        Pool, Wt + 3 * D_ * D_, bo, out, BLn,
        Pool, Wt + 3 * D_ * D_, bo, out, BLn,
        Pool, Wt + 3 * D_ * D_, bo, out, BLn);
}

// round 9
// speedup vs baseline: 1.0803x; 1.0803x over previous
#include <cuda_runtime.h>
#include <math.h>

// Problem constants
#define D_  768
#define H_  12
#define E_  64
#define S_  2000
#define MQ  2048    // B*L*TQ
#define BLn 256     // B*L
#define TQn 8
#define NSPLIT 3

// Scratch (device globals: allocation-free)
__device__ float g_Xq[MQ * D_];
__device__ float g_Xk[S_ * D_];
__device__ float g_Xv[S_ * D_];
__device__ float g_Qb[MQ * D_];               // tf32 bits (gemm cvtOut=1)
__device__ float g_Kb[S_ * D_];               // tf32 bits
__device__ float g_Vb[S_ * D_];               // tf32 bits
__device__ float g_Oacc[NSPLIT * MQ * D_];    // unnormalized per-split attn out
__device__ float g_ML[NSPLIT * MQ * H_ * 2];  // per-split (m, l)
__device__ float g_Pool[BLn * D_];

// ---------------------------------------------------------------------------
// helpers
// ---------------------------------------------------------------------------
__device__ __forceinline__ unsigned f2tf(float x) {
    unsigned r;
    asm("cvt.rna.tf32.f32 %0, %1;" : "=r"(r) : "f"(x));
    return r;
}

__device__ __forceinline__ void mma_tf32(float* d, const unsigned* a,
                                         unsigned b0, unsigned b1) {
    asm volatile(
        "mma.sync.aligned.m16n8k8.row.col.f32.tf32.tf32.f32 "
        "{%0,%1,%2,%3},{%4,%5,%6,%7},{%8,%9},{%0,%1,%2,%3};\n"
        : "+f"(d[0]), "+f"(d[1]), "+f"(d[2]), "+f"(d[3])
        : "r"(a[0]), "r"(a[1]), "r"(a[2]), "r"(a[3]), "r"(b0), "r"(b1));
}

// ---------------------------------------------------------------------------
// Fused LayerNorm: one launch covers target (2048 rows) + key (2000) + value
// (2000). One block per row, 256 threads.
// ---------------------------------------------------------------------------
__global__ void ln3_kernel(const float* __restrict__ tgt, float* __restrict__ Xq,
                           const float* __restrict__ gq, const float* __restrict__ bq_,
                           const float* __restrict__ key, const float* __restrict__ val,
                           float* __restrict__ Xk, float* __restrict__ Xv,
                           const float* __restrict__ gkv, const float* __restrict__ bkv) {
    int row = blockIdx.x;
    const float *x, *g, *b;
    float* y;
    if (row < MQ) {
        x = tgt + (size_t)row * D_; y = Xq + (size_t)row * D_; g = gq; b = bq_;
    } else if (row < MQ + S_) {
        int r = row - MQ;
        x = key + (size_t)r * D_; y = Xk + (size_t)r * D_; g = gkv; b = bkv;
    } else {
        int r = row - MQ - S_;
        x = val + (size_t)r * D_; y = Xv + (size_t)r * D_; g = gkv; b = bkv;
    }

    int t = threadIdx.x;
    float v0 = x[t], v1 = x[t + 256], v2 = x[t + 512];
    float s  = v0 + v1 + v2;
    float ss = v0 * v0 + v1 * v1 + v2 * v2;

    __shared__ float redS[8], redQ[8];
    #pragma unroll
    for (int o = 16; o > 0; o >>= 1) {
        s  += __shfl_xor_sync(0xffffffffu, s, o);
        ss += __shfl_xor_sync(0xffffffffu, ss, o);
    }
    int warp = t >> 5, lane = t & 31;
    if (lane == 0) { redS[warp] = s; redQ[warp] = ss; }
    __syncthreads();
    float sum = 0.f, sq = 0.f;
    #pragma unroll
    for (int w = 0; w < 8; w++) { sum += redS[w]; sq += redQ[w]; }

    float mean = sum * (1.0f / D_);
    float var  = sq * (1.0f / D_) - mean * mean;
    float rs   = rsqrtf(var + 1e-5f);

    y[t]       = (v0 - mean) * rs * g[t]       + b[t];
    y[t + 256] = (v1 - mean) * rs * g[t + 256] + b[t + 256];
    y[t + 512] = (v2 - mean) * rs * g[t + 512] + b[t + 512];
}

// ---------------------------------------------------------------------------
// Batched TF32 GEMM (R2/R6 mainloop verbatim): C[M][768] = A @ W^T + bias
// cvtOut=1: store tf32 bit patterns (for attention operands); 0: store fp32.
// ---------------------------------------------------------------------------
__global__ __launch_bounds__(256, 2)
void gemm3_tf32(const float* A0, const float* W0, const float* bi0, float* C0, int M0,
                const float* A1, const float* W1, const float* bi1, float* C1, int M1,
                const float* A2, const float* W2, const float* bi2, float* C2, int M2,
                int cvtOut) {
    const float* A; const float* W; const float* bias; float* C; int M;
    if (blockIdx.z == 0) { A = A0; W = W0; bias = bi0; C = C0; M = M0; }
    else if (blockIdx.z == 1) { A = A1; W = W1; bias = bi1; C = C1; M = M1; }
    else { A = A2; W = W2; bias = bi2; C = C2; M = M2; }

    __shared__ unsigned As[128 * 36];
    __shared__ unsigned Ws[128 * 36];

    int t = threadIdx.x, w = t >> 5, lane = t & 31;
    int g = lane >> 2, c = lane & 3;
    int wm = w >> 2, wn = w & 3;
    int row0 = blockIdx.y * 128;
    int col0 = blockIdx.x * 128;

    float acc[4][4][4];
    #pragma unroll
    for (int i = 0; i < 4; i++)
        #pragma unroll
        for (int j = 0; j < 4; j++)
            #pragma unroll
            for (int k = 0; k < 4; k++) acc[i][j][k] = 0.f;

    for (int k0 = 0; k0 < D_; k0 += 32) {
        __syncthreads();
        #pragma unroll
        for (int i = t; i < 1024; i += 256) {
            int r = i >> 3, kq = (i & 7) << 2;
            int ar = row0 + r;
            float4 av = make_float4(0.f, 0.f, 0.f, 0.f);
            if (ar < M) av = *(const float4*)(A + (size_t)ar * D_ + k0 + kq);
            uint4 ua = make_uint4(f2tf(av.x), f2tf(av.y), f2tf(av.z), f2tf(av.w));
            *(uint4*)&As[r * 36 + kq] = ua;

            float4 wv = *(const float4*)(W + (size_t)(col0 + r) * D_ + k0 + kq);
            uint4 uw = make_uint4(f2tf(wv.x), f2tf(wv.y), f2tf(wv.z), f2tf(wv.w));
            *(uint4*)&Ws[r * 36 + kq] = uw;
        }
        __syncthreads();

        #pragma unroll
        for (int ks = 0; ks < 4; ks++) {
            int kk = ks * 8;
            unsigned a[4][4];
            #pragma unroll
            for (int mt = 0; mt < 4; mt++) {
                int base = wm * 64 + mt * 16;
                a[mt][0] = As[(base + g)     * 36 + kk + c];
                a[mt][1] = As[(base + g + 8) * 36 + kk + c];
                a[mt][2] = As[(base + g)     * 36 + kk + 4 + c];
                a[mt][3] = As[(base + g + 8) * 36 + kk + 4 + c];
            }
            #pragma unroll
            for (int nt = 0; nt < 4; nt++) {
                int n = wn * 32 + nt * 8 + g;
                unsigned b0 = Ws[n * 36 + kk + c];
                unsigned b1 = Ws[n * 36 + kk + 4 + c];
                #pragma unroll
                for (int mt = 0; mt < 4; mt++)
                    mma_tf32(acc[mt][nt], a[mt], b0, b1);
            }
        }
    }

    #pragma unroll
    for (int mt = 0; mt < 4; mt++) {
        int rA = row0 + wm * 64 + mt * 16 + g;
        int rB = rA + 8;
        #pragma unroll
        for (int nt = 0; nt < 4; nt++) {
            int colb = col0 + wn * 32 + nt * 8 + 2 * c;
            float b0v = bias[colb], b1v = bias[colb + 1];
            float v00 = acc[mt][nt][0] + b0v, v01 = acc[mt][nt][1] + b1v;
            float v10 = acc[mt][nt][2] + b0v, v11 = acc[mt][nt][3] + b1v;
            if (cvtOut) {
                v00 = __uint_as_float(f2tf(v00)); v01 = __uint_as_float(f2tf(v01));
                v10 = __uint_as_float(f2tf(v10)); v11 = __uint_as_float(f2tf(v11));
            }
            if (rA < M) {
                C[(size_t)rA * D_ + colb]     = v00;
                C[(size_t)rA * D_ + colb + 1] = v01;
            }
            if (rB < M) {
                C[(size_t)rB * D_ + colb]     = v10;
                C[(size_t)rB * D_ + colb + 1] = v11;
            }
        }
    }
}

// ---------------------------------------------------------------------------
// TF32 flash attention v3 (R6 mainloop): register-P PV via permuted K,
// ASC=32, occ 2, split-KV x3. Q/K/V arrive as PRE-CONVERTED tf32 bits, so
// staging is a pure copy. grid (8,12,3) = 288 CTAs, one wave.
// ---------------------------------------------------------------------------
#define AQT 256
#define ASC 32
#define NCH ((S_ + ASC - 1) / ASC)              /* 63 */
#define CHSPLIT ((NCH + NSPLIT - 1) / NSPLIT)   /* 21 */
#define ATTN_WORDS (AQT*68 + ASC*68 + ASC*72 + ASC)
#define ATTN_SMEM  (ATTN_WORDS * 4)

__global__ __launch_bounds__(256, 2)
void attn_tf32(const unsigned* __restrict__ Q, const unsigned* __restrict__ K,
               const unsigned* __restrict__ V, const int* __restrict__ mask,
               float* __restrict__ Oacc, float* __restrict__ ML) {
    extern __shared__ unsigned smu[];
    unsigned* Qs = smu;                      // [256][68]
    unsigned* Ks = Qs + AQT * 68;            // [32][68]
    unsigned* Vs = Ks + ASC * 68;            // [32][72] rows permuted
    float* maskAdd = (float*)(Vs + ASC * 72);// [32]

    int h = blockIdx.y;
    int z = blockIdx.z;
    int row0 = blockIdx.x * AQT;
    int t = threadIdx.x, w = t >> 5, lane = t & 31;
    int g = lane >> 2, c = lane & 3;
    int wrow = w * 32;

    // load Q tile (already tf32 bits)
    #pragma unroll 4
    for (int i = t; i < AQT * 16; i += 256) {
        int r = i >> 4, e4 = (i & 15) << 2;
        uint4 q4 = *(const uint4*)(Q + (size_t)(row0 + r) * D_ + h * E_ + e4);
        *(uint4*)&Qs[r * 68 + e4] = q4;
    }

    float mA[2] = {-1e30f, -1e30f}, mB[2] = {-1e30f, -1e30f};
    float lA[2] = {0.f, 0.f}, lB[2] = {0.f, 0.f};
    float acc[2][8][4];
    #pragma unroll
    for (int mt = 0; mt < 2; mt++)
        #pragma unroll
        for (int nt = 0; nt < 8; nt++)
            #pragma unroll
            for (int k = 0; k < 4; k++) acc[mt][nt][k] = 0.f;

    int chBeg = z * CHSPLIT;
    int chEnd = min(chBeg + CHSPLIT, NCH);
    for (int ch = chBeg; ch < chEnd; ch++) {
        int s0 = ch * ASC;
        __syncthreads();

        // stage K (natural rows) and V (permuted rows); zero tail
        #pragma unroll 2
        for (int i = t; i < ASC * 16; i += 256) {
            int s = i >> 4, e4 = (i & 15) << 2;
            int gs = s0 + s;
            uint4 kv = make_uint4(0u, 0u, 0u, 0u);
            uint4 vv = make_uint4(0u, 0u, 0u, 0u);
            if (gs < S_) {
                kv = *(const uint4*)(K + (size_t)gs * D_ + h * E_ + e4);
                vv = *(const uint4*)(V + (size_t)gs * D_ + h * E_ + e4);
            }
            *(uint4*)&Ks[s * 68 + e4] = kv;
            int sw = s & 7;
            int sp = (s & ~7) | ((sw & 1) ? 4 + (sw >> 1) : (sw >> 1));
            *(uint4*)&Vs[sp * 72 + e4] = vv;
        }
        if (t < ASC) {
            int gs = s0 + t;
            maskAdd[t] = (gs < S_ && mask[gs] != 0) ? 0.f : -1e30f;
        }
        __syncthreads();

        // ---- scores = Q @ K^T  (32 cols) ----
        float sc[2][4][4];
        #pragma unroll
        for (int mt = 0; mt < 2; mt++)
            #pragma unroll
            for (int nt = 0; nt < 4; nt++)
                #pragma unroll
                for (int k = 0; k < 4; k++) sc[mt][nt][k] = 0.f;

        #pragma unroll
        for (int ks = 0; ks < 8; ks++) {
            int k0 = ks * 8;
            unsigned a[2][4];
            #pragma unroll
            for (int mt = 0; mt < 2; mt++) {
                int base = wrow + mt * 16;
                a[mt][0] = Qs[(base + g)     * 68 + k0 + c];
                a[mt][1] = Qs[(base + g + 8) * 68 + k0 + c];
                a[mt][2] = Qs[(base + g)     * 68 + k0 + 4 + c];
                a[mt][3] = Qs[(base + g + 8) * 68 + k0 + 4 + c];
            }
            #pragma unroll
            for (int nt = 0; nt < 4; nt++) {
                int n0 = nt * 8;
                unsigned b0 = Ks[(n0 + g) * 68 + k0 + c];
                unsigned b1 = Ks[(n0 + g) * 68 + k0 + 4 + c];
                mma_tf32(sc[0][nt], a[0], b0, b1);
                mma_tf32(sc[1][nt], a[1], b0, b1);
            }
        }

        // ---- online softmax; exp'd P stays in registers ----
        #pragma unroll
        for (int mt = 0; mt < 2; mt++) {
            float mxA = -1e30f, mxB = -1e30f;
            #pragma unroll
            for (int nt = 0; nt < 4; nt++) {
                int j0 = nt * 8 + 2 * c;
                float ma0 = maskAdd[j0], ma1 = maskAdd[j0 + 1];
                sc[mt][nt][0] = sc[mt][nt][0] * 0.125f + ma0;
                sc[mt][nt][1] = sc[mt][nt][1] * 0.125f + ma1;
                sc[mt][nt][2] = sc[mt][nt][2] * 0.125f + ma0;
                sc[mt][nt][3] = sc[mt][nt][3] * 0.125f + ma1;
                mxA = fmaxf(mxA, fmaxf(sc[mt][nt][0], sc[mt][nt][1]));
                mxB = fmaxf(mxB, fmaxf(sc[mt][nt][2], sc[mt][nt][3]));
            }
            mxA = fmaxf(mxA, __shfl_xor_sync(0xffffffffu, mxA, 1));
            mxA = fmaxf(mxA, __shfl_xor_sync(0xffffffffu, mxA, 2));
            mxB = fmaxf(mxB, __shfl_xor_sync(0xffffffffu, mxB, 1));
            mxB = fmaxf(mxB, __shfl_xor_sync(0xffffffffu, mxB, 2));

            float mnA = fmaxf(mA[mt], mxA);
            float mnB = fmaxf(mB[mt], mxB);
            float corrA = __expf(mA[mt] - mnA);
            float corrB = __expf(mB[mt] - mnB);
            mA[mt] = mnA; mB[mt] = mnB;

            float psA = 0.f, psB = 0.f;
            #pragma unroll
            for (int nt = 0; nt < 4; nt++) {
                float p0 = __expf(sc[mt][nt][0] - mnA);
                float p1 = __expf(sc[mt][nt][1] - mnA);
                float p2 = __expf(sc[mt][nt][2] - mnB);
                float p3 = __expf(sc[mt][nt][3] - mnB);
                psA += p0 + p1; psB += p2 + p3;
                sc[mt][nt][0] = __uint_as_float(f2tf(p0));
                sc[mt][nt][1] = __uint_as_float(f2tf(p1));
                sc[mt][nt][2] = __uint_as_float(f2tf(p2));
                sc[mt][nt][3] = __uint_as_float(f2tf(p3));
            }
            psA += __shfl_xor_sync(0xffffffffu, psA, 1);
            psA += __shfl_xor_sync(0xffffffffu, psA, 2);
            psB += __shfl_xor_sync(0xffffffffu, psB, 1);
            psB += __shfl_xor_sync(0xffffffffu, psB, 2);
            lA[mt] = lA[mt] * corrA + psA;
            lB[mt] = lB[mt] * corrB + psB;
            #pragma unroll
            for (int nt = 0; nt < 8; nt++) {
                acc[mt][nt][0] *= corrA; acc[mt][nt][1] *= corrA;
                acc[mt][nt][2] *= corrB; acc[mt][nt][3] *= corrB;
            }
        }

        // ---- acc += P @ V (register A-operands, permuted-K V) ----
        #pragma unroll
        for (int ks = 0; ks < 4; ks++) {
            int k0 = ks * 8;
            unsigned aP[2][4];
            #pragma unroll
            for (int mt = 0; mt < 2; mt++) {
                aP[mt][0] = __float_as_uint(sc[mt][ks][0]);
                aP[mt][1] = __float_as_uint(sc[mt][ks][2]);
                aP[mt][2] = __float_as_uint(sc[mt][ks][1]);
                aP[mt][3] = __float_as_uint(sc[mt][ks][3]);
            }
            #pragma unroll
            for (int nt = 0; nt < 8; nt++) {
                int e0 = nt * 8;
                unsigned b0 = Vs[(k0 + c)     * 72 + e0 + g];
                unsigned b1 = Vs[(k0 + 4 + c) * 72 + e0 + g];
                mma_tf32(acc[0][nt], aP[0], b0, b1);
                mma_tf32(acc[1][nt], aP[1], b0, b1);
            }
        }
    }

    // epilogue: store unnormalized acc + (m,l)
    #pragma unroll
    for (int mt = 0; mt < 2; mt++) {
        int rA = row0 + wrow + mt * 16 + g;
        int rB = rA + 8;
        float* obase = Oacc + (size_t)z * MQ * D_;
        #pragma unroll
        for (int nt = 0; nt < 8; nt++) {
            int col = h * E_ + nt * 8 + 2 * c;
            *(float2*)&obase[(size_t)rA * D_ + col] =
                make_float2(acc[mt][nt][0], acc[mt][nt][1]);
            *(float2*)&obase[(size_t)rB * D_ + col] =
                make_float2(acc[mt][nt][2], acc[mt][nt][3]);
        }
        if (c == 0) {
            size_t iA = ((size_t)(z * MQ + rA) * H_ + h) * 2;
            size_t iB = ((size_t)(z * MQ + rB) * H_ + h) * 2;
            ML[iA]     = mA[mt]; ML[iA + 1] = lA[mt];
            ML[iB]     = mB[mt]; ML[iB + 1] = lB[mt];
        }
    }
}

// ---------------------------------------------------------------------------
// Split-KV combine + mean-pool over TQ=8: (3,2048,768) -> (256,768)
// ---------------------------------------------------------------------------
__global__ void combine_pool_kernel(const float* __restrict__ Oacc,
                                    const float* __restrict__ ML,
                                    float* __restrict__ P) {
    int idx = blockIdx.x * 256 + threadIdx.x;
    if (idx >= BLn * D_) return;
    int bl = idx / D_, d = idx % D_;
    int h = d >> 6;
    float s = 0.f;
    #pragma unroll
    for (int tq = 0; tq < TQn; tq++) {
        int row = bl * TQn + tq;
        size_t i0 = ((size_t)(0 * MQ + row) * H_ + h) * 2;
        size_t i1 = ((size_t)(1 * MQ + row) * H_ + h) * 2;
        size_t i2 = ((size_t)(2 * MQ + row) * H_ + h) * 2;
        float m0 = ML[i0], l0 = ML[i0 + 1];
        float m1 = ML[i1], l1 = ML[i1 + 1];
        float m2 = ML[i2], l2 = ML[i2 + 1];
        float M = fmaxf(m0, fmaxf(m1, m2));
        float w0 = __expf(m0 - M), w1 = __expf(m1 - M), w2 = __expf(m2 - M);
        float denom = l0 * w0 + l1 * w1 + l2 * w2;
        float a0 = Oacc[(size_t)(0 * MQ + row) * D_ + d];
        float a1 = Oacc[(size_t)(1 * MQ + row) * D_ + d];
        float a2 = Oacc[(size_t)(2 * MQ + row) * D_ + d];
        s += (a0 * w0 + a1 * w1 + a2 * w2) / denom;
    }
    P[idx] = s * (1.0f / TQn);
}

// ---------------------------------------------------------------------------
extern "C" void kernel_launch(void* const* d_in, const int* in_sizes, int n_in,
                              void* d_out, int out_size) {
    const float* target     = (const float*)d_in[0];
    const float* key_bank   = (const float*)d_in[1];
    const float* value_bank = (const float*)d_in[2];
    const int*   bank_mask  = (const int*)  d_in[3];
    const float* Wq = (const float*)d_in[4];
    const float* bq = (const float*)d_in[5];
    const float* Wk = (const float*)d_in[6];
    const float* bk = (const float*)d_in[7];
    const float* Wv = (const float*)d_in[8];
    const float* bv = (const float*)d_in[9];
    const float* Wo = (const float*)d_in[10];
    const float* bo = (const float*)d_in[11];
    const float* gq = (const float*)d_in[12];
    const float* betaq = (const float*)d_in[13];
    const float* gkv = (const float*)d_in[14];
    const float* betakv = (const float*)d_in[15];
    float* out = (float*)d_out;

    float *Xq, *Xk, *Xv, *Qb, *Kb, *Vb, *Oacc, *ML, *Pool;
    cudaGetSymbolAddress((void**)&Xq,  g_Xq);
    cudaGetSymbolAddress((void**)&Xk,  g_Xk);
    cudaGetSymbolAddress((void**)&Xv,  g_Xv);
    cudaGetSymbolAddress((void**)&Qb,  g_Qb);
    cudaGetSymbolAddress((void**)&Kb,  g_Kb);
    cudaGetSymbolAddress((void**)&Vb,  g_Vb);
    cudaGetSymbolAddress((void**)&Oacc, g_Oacc);
    cudaGetSymbolAddress((void**)&ML,  g_ML);
    cudaGetSymbolAddress((void**)&Pool, g_Pool);

    cudaFuncSetAttribute(attn_tf32,
                         cudaFuncAttributeMaxDynamicSharedMemorySize, ATTN_SMEM);

    // 1. Fused LayerNorms (one launch, 6048 blocks)
    ln3_kernel<<<MQ + 2 * S_, 256>>>(target, Xq, gq, betaq,
                                     key_bank, value_bank, Xk, Xv, gkv, betakv);

    // 2. Q/K/V projections (288 CTAs); outputs stored as tf32 bit patterns
    gemm3_tf32<<<dim3(D_ / 128, 16, 3), 256>>>(
        Xq, Wq, bq, Qb, MQ,
        Xk, Wk, bk, Kb, S_,
        Xv, Wv, bv, Vb, S_, 1);

    // 3. Attention: split-KV x3, occ 2 => 288 CTAs in ONE wave
    attn_tf32<<<dim3(MQ / AQT, H_, NSPLIT), 256, ATTN_SMEM>>>(
        (const unsigned*)Qb, (const unsigned*)Kb, (const unsigned*)Vb,
        bank_mask, Oacc, ML);

    // 4. Combine splits + mean-pool over TQ
    combine_pool_kernel<<<(BLn * D_ + 255) / 256, 256>>>(Oacc, ML, Pool);

    // 5. Output projection (fp32 out)
    gemm3_tf32<<<dim3(D_ / 128, 2, 1), 256>>>(
        Pool, Wo, bo, out, BLn,
        Pool, Wo, bo, out, BLn,
        Pool, Wo, bo, out, BLn, 0);
}

// round 10
// speedup vs baseline: 1.0877x; 1.0068x over previous
#include <cuda_runtime.h>
#include <math.h>

// Problem constants
#define D_  768
#define H_  12
#define E_  64
#define S_  2000
#define MQ  2048    // B*L*TQ
#define BLn 256     // B*L
#define TQn 8
#define NSPLIT 3

// Scratch (device globals: allocation-free)
__device__ float g_Xq[MQ * D_];
__device__ float g_Xk[S_ * D_];
__device__ float g_Xv[S_ * D_];
__device__ float g_Qb[MQ * D_];               // tf32 bits (gemm cvtOut=1)
__device__ float g_Kb[S_ * D_];               // tf32 bits
__device__ float g_Vb[S_ * D_];               // tf32 bits
__device__ float g_Oacc[NSPLIT * MQ * D_];    // unnormalized per-split attn out
__device__ float g_ML[NSPLIT * MQ * H_ * 2];  // per-split (m, l)
__device__ float g_Pool[BLn * D_];

// ---------------------------------------------------------------------------
// helpers
// ---------------------------------------------------------------------------
__device__ __forceinline__ unsigned f2tf(float x) {
    unsigned r;
    asm("cvt.rna.tf32.f32 %0, %1;" : "=r"(r) : "f"(x));
    return r;
}

__device__ __forceinline__ void mma_tf32(float* d, const unsigned* a,
                                         unsigned b0, unsigned b1) {
    asm volatile(
        "mma.sync.aligned.m16n8k8.row.col.f32.tf32.tf32.f32 "
        "{%0,%1,%2,%3},{%4,%5,%6,%7},{%8,%9},{%0,%1,%2,%3};\n"
        : "+f"(d[0]), "+f"(d[1]), "+f"(d[2]), "+f"(d[3])
        : "r"(a[0]), "r"(a[1]), "r"(a[2]), "r"(a[3]), "r"(b0), "r"(b1));
}

__device__ __forceinline__ void cp16(unsigned* dst_smem, const void* src, bool valid) {
    unsigned daddr = (unsigned)__cvta_generic_to_shared(dst_smem);
    int sz = valid ? 16 : 0;
    asm volatile("cp.async.cg.shared.global [%0], [%1], 16, %2;\n"
                 :: "r"(daddr), "l"(src), "r"(sz));
}
__device__ __forceinline__ void cp_commit() {
    asm volatile("cp.async.commit_group;\n");
}
template <int N>
__device__ __forceinline__ void cp_wait() {
    asm volatile("cp.async.wait_group %0;\n" :: "n"(N));
}

// ---------------------------------------------------------------------------
// Fused LayerNorm: target (2048) + key (2000) + value (2000) in one launch.
// ---------------------------------------------------------------------------
__global__ void ln3_kernel(const float* __restrict__ tgt, float* __restrict__ Xq,
                           const float* __restrict__ gq, const float* __restrict__ bq_,
                           const float* __restrict__ key, const float* __restrict__ val,
                           float* __restrict__ Xk, float* __restrict__ Xv,
                           const float* __restrict__ gkv, const float* __restrict__ bkv) {
    int row = blockIdx.x;
    const float *x, *g, *b;
    float* y;
    if (row < MQ) {
        x = tgt + (size_t)row * D_; y = Xq + (size_t)row * D_; g = gq; b = bq_;
    } else if (row < MQ + S_) {
        int r = row - MQ;
        x = key + (size_t)r * D_; y = Xk + (size_t)r * D_; g = gkv; b = bkv;
    } else {
        int r = row - MQ - S_;
        x = val + (size_t)r * D_; y = Xv + (size_t)r * D_; g = gkv; b = bkv;
    }

    int t = threadIdx.x;
    float v0 = x[t], v1 = x[t + 256], v2 = x[t + 512];
    float s  = v0 + v1 + v2;
    float ss = v0 * v0 + v1 * v1 + v2 * v2;

    __shared__ float redS[8], redQ[8];
    #pragma unroll
    for (int o = 16; o > 0; o >>= 1) {
        s  += __shfl_xor_sync(0xffffffffu, s, o);
        ss += __shfl_xor_sync(0xffffffffu, ss, o);
    }
    int warp = t >> 5, lane = t & 31;
    if (lane == 0) { redS[warp] = s; redQ[warp] = ss; }
    __syncthreads();
    float sum = 0.f, sq = 0.f;
    #pragma unroll
    for (int w = 0; w < 8; w++) { sum += redS[w]; sq += redQ[w]; }

    float mean = sum * (1.0f / D_);
    float var  = sq * (1.0f / D_) - mean * mean;
    float rs   = rsqrtf(var + 1e-5f);

    y[t]       = (v0 - mean) * rs * g[t]       + b[t];
    y[t + 256] = (v1 - mean) * rs * g[t + 256] + b[t + 256];
    y[t + 512] = (v2 - mean) * rs * g[t + 512] + b[t + 512];
}

// ---------------------------------------------------------------------------
// Batched TF32 GEMM (R2/R6 mainloop verbatim): C[M][768] = A @ W^T + bias
// cvtOut=1: store tf32 bit patterns; 0: store fp32.
// ---------------------------------------------------------------------------
__global__ __launch_bounds__(256, 2)
void gemm3_tf32(const float* A0, const float* W0, const float* bi0, float* C0, int M0,
                const float* A1, const float* W1, const float* bi1, float* C1, int M1,
                const float* A2, const float* W2, const float* bi2, float* C2, int M2,
                int cvtOut) {
    const float* A; const float* W; const float* bias; float* C; int M;
    if (blockIdx.z == 0) { A = A0; W = W0; bias = bi0; C = C0; M = M0; }
    else if (blockIdx.z == 1) { A = A1; W = W1; bias = bi1; C = C1; M = M1; }
    else { A = A2; W = W2; bias = bi2; C = C2; M = M2; }

    __shared__ unsigned As[128 * 36];
    __shared__ unsigned Ws[128 * 36];

    int t = threadIdx.x, w = t >> 5, lane = t & 31;
    int g = lane >> 2, c = lane & 3;
    int wm = w >> 2, wn = w & 3;
    int row0 = blockIdx.y * 128;
    int col0 = blockIdx.x * 128;

    float acc[4][4][4];
    #pragma unroll
    for (int i = 0; i < 4; i++)
        #pragma unroll
        for (int j = 0; j < 4; j++)
            #pragma unroll
            for (int k = 0; k < 4; k++) acc[i][j][k] = 0.f;

    for (int k0 = 0; k0 < D_; k0 += 32) {
        __syncthreads();
        #pragma unroll
        for (int i = t; i < 1024; i += 256) {
            int r = i >> 3, kq = (i & 7) << 2;
            int ar = row0 + r;
            float4 av = make_float4(0.f, 0.f, 0.f, 0.f);
            if (ar < M) av = *(const float4*)(A + (size_t)ar * D_ + k0 + kq);
            uint4 ua = make_uint4(f2tf(av.x), f2tf(av.y), f2tf(av.z), f2tf(av.w));
            *(uint4*)&As[r * 36 + kq] = ua;

            float4 wv = *(const float4*)(W + (size_t)(col0 + r) * D_ + k0 + kq);
            uint4 uw = make_uint4(f2tf(wv.x), f2tf(wv.y), f2tf(wv.z), f2tf(wv.w));
            *(uint4*)&Ws[r * 36 + kq] = uw;
        }
        __syncthreads();

        #pragma unroll
        for (int ks = 0; ks < 4; ks++) {
            int kk = ks * 8;
            unsigned a[4][4];
            #pragma unroll
            for (int mt = 0; mt < 4; mt++) {
                int base = wm * 64 + mt * 16;
                a[mt][0] = As[(base + g)     * 36 + kk + c];
                a[mt][1] = As[(base + g + 8) * 36 + kk + c];
                a[mt][2] = As[(base + g)     * 36 + kk + 4 + c];
                a[mt][3] = As[(base + g + 8) * 36 + kk + 4 + c];
            }
            #pragma unroll
            for (int nt = 0; nt < 4; nt++) {
                int n = wn * 32 + nt * 8 + g;
                unsigned b0 = Ws[n * 36 + kk + c];
                unsigned b1 = Ws[n * 36 + kk + 4 + c];
                #pragma unroll
                for (int mt = 0; mt < 4; mt++)
                    mma_tf32(acc[mt][nt], a[mt], b0, b1);
            }
        }
    }

    #pragma unroll
    for (int mt = 0; mt < 4; mt++) {
        int rA = row0 + wm * 64 + mt * 16 + g;
        int rB = rA + 8;
        #pragma unroll
        for (int nt = 0; nt < 4; nt++) {
            int colb = col0 + wn * 32 + nt * 8 + 2 * c;
            float b0v = bias[colb], b1v = bias[colb + 1];
            float v00 = acc[mt][nt][0] + b0v, v01 = acc[mt][nt][1] + b1v;
            float v10 = acc[mt][nt][2] + b0v, v11 = acc[mt][nt][3] + b1v;
            if (cvtOut) {
                v00 = __uint_as_float(f2tf(v00)); v01 = __uint_as_float(f2tf(v01));
                v10 = __uint_as_float(f2tf(v10)); v11 = __uint_as_float(f2tf(v11));
            }
            if (rA < M) {
                C[(size_t)rA * D_ + colb]     = v00;
                C[(size_t)rA * D_ + colb + 1] = v01;
            }
            if (rB < M) {
                C[(size_t)rB * D_ + colb]     = v10;
                C[(size_t)rB * D_ + colb + 1] = v11;
            }
        }
    }
}

// ---------------------------------------------------------------------------
// TF32 flash attention v4: cp.async double-buffered K/V prefetch, hoisted
// per-CTA mask addends, register-P PV, ASC=32, occ 2, split-KV x3.
// grid (8, 12, 3) = 288 CTAs, one wave. smem 105.8 KB.
// ---------------------------------------------------------------------------
#define AQT 256
#define ASC 32
#define NCH ((S_ + ASC - 1) / ASC)              /* 63 */
#define CHSPLIT ((NCH + NSPLIT - 1) / NSPLIT)   /* 21 */
#define KBUF (ASC * 68)
#define VBUF (ASC * 72)
// Qs 256*68 + 2*Ks + 2*Vs + mask 672
#define ATTN_WORDS (AQT*68 + 2*KBUF + 2*VBUF + CHSPLIT*ASC)
#define ATTN_SMEM  (ATTN_WORDS * 4)

__global__ __launch_bounds__(256, 2)
void attn_tf32(const unsigned* __restrict__ Q, const unsigned* __restrict__ K,
               const unsigned* __restrict__ V, const int* __restrict__ mask,
               float* __restrict__ Oacc, float* __restrict__ ML) {
    extern __shared__ unsigned smu[];
    unsigned* Qs = smu;                        // [256][68]
    unsigned* Ks0 = Qs + AQT * 68;             // 2 x [32][68]
    unsigned* Vs0 = Ks0 + 2 * KBUF;            // 2 x [32][72] rows permuted
    float* maskSm = (float*)(Vs0 + 2 * VBUF);  // [CHSPLIT*32] addends

    int h = blockIdx.y;
    int z = blockIdx.z;
    int row0 = blockIdx.x * AQT;
    int t = threadIdx.x, w = t >> 5, lane = t & 31;
    int g = lane >> 2, c = lane & 3;
    int wrow = w * 32;

    int chBeg = z * CHSPLIT;
    int chEnd = min(chBeg + CHSPLIT, NCH);

    // load Q tile (already tf32 bits)
    #pragma unroll 4
    for (int i = t; i < AQT * 16; i += 256) {
        int r = i >> 4, e4 = (i & 15) << 2;
        uint4 q4 = *(const uint4*)(Q + (size_t)(row0 + r) * D_ + h * E_ + e4);
        *(uint4*)&Qs[r * 68 + e4] = q4;
    }
    // hoist mask for this CTA's whole split (once)
    for (int i = t; i < CHSPLIT * ASC; i += 256) {
        int gs = chBeg * ASC + i;
        maskSm[i] = (gs < S_ && mask[gs] != 0) ? 0.f : -1e30f;
    }

    // staging via cp.async: each thread covers 2 (s,e4) slots of K and V
    auto stageKV = [&](int ch, int buf) {
        unsigned* Ks = Ks0 + buf * KBUF;
        unsigned* Vs = Vs0 + buf * VBUF;
        int s0 = ch * ASC;
        #pragma unroll
        for (int i = t; i < ASC * 16; i += 256) {
            int s = i >> 4, e4 = (i & 15) << 2;
            int gs = s0 + s;
            bool ok = gs < S_;
            const unsigned* ksrc = K + (size_t)gs * D_ + h * E_ + e4;
            const unsigned* vsrc = V + (size_t)gs * D_ + h * E_ + e4;
            cp16(&Ks[s * 68 + e4], ksrc, ok);
            int sw = s & 7;
            int sp = (s & ~7) | ((sw & 1) ? 4 + (sw >> 1) : (sw >> 1));
            cp16(&Vs[sp * 72 + e4], vsrc, ok);
        }
        cp_commit();
    };

    float mA[2] = {-1e30f, -1e30f}, mB[2] = {-1e30f, -1e30f};
    float lA[2] = {0.f, 0.f}, lB[2] = {0.f, 0.f};
    float acc[2][8][4];
    #pragma unroll
    for (int mt = 0; mt < 2; mt++)
        #pragma unroll
        for (int nt = 0; nt < 8; nt++)
            #pragma unroll
            for (int k = 0; k < 4; k++) acc[mt][nt][k] = 0.f;

    stageKV(chBeg, 0);

    for (int ch = chBeg; ch < chEnd; ch++) {
        int buf = (ch - chBeg) & 1;
        __syncthreads();   // guard: all readers of buf^1 (iter ch-1) done
        if (ch + 1 < chEnd) {
            stageKV(ch + 1, buf ^ 1);
            cp_wait<1>();
        } else {
            cp_wait<0>();
        }
        __syncthreads();   // staged data visible block-wide

        const unsigned* Ks = Ks0 + buf * KBUF;
        const unsigned* Vs = Vs0 + buf * VBUF;
        const float* maskAdd = maskSm + (ch - chBeg) * ASC;

        // ---- scores = Q @ K^T  (32 cols) ----
        float sc[2][4][4];
        #pragma unroll
        for (int mt = 0; mt < 2; mt++)
            #pragma unroll
            for (int nt = 0; nt < 4; nt++)
                #pragma unroll
                for (int k = 0; k < 4; k++) sc[mt][nt][k] = 0.f;

        #pragma unroll
        for (int ks = 0; ks < 8; ks++) {
            int k0 = ks * 8;
            unsigned a[2][4];
            #pragma unroll
            for (int mt = 0; mt < 2; mt++) {
                int base = wrow + mt * 16;
                a[mt][0] = Qs[(base + g)     * 68 + k0 + c];
                a[mt][1] = Qs[(base + g + 8) * 68 + k0 + c];
                a[mt][2] = Qs[(base + g)     * 68 + k0 + 4 + c];
                a[mt][3] = Qs[(base + g + 8) * 68 + k0 + 4 + c];
            }
            #pragma unroll
            for (int nt = 0; nt < 4; nt++) {
                int n0 = nt * 8;
                unsigned b0 = Ks[(n0 + g) * 68 + k0 + c];
                unsigned b1 = Ks[(n0 + g) * 68 + k0 + 4 + c];
                mma_tf32(sc[0][nt], a[0], b0, b1);
                mma_tf32(sc[1][nt], a[1], b0, b1);
            }
        }

        // ---- online softmax; exp'd P stays in registers ----
        #pragma unroll
        for (int mt = 0; mt < 2; mt++) {
            float mxA = -1e30f, mxB = -1e30f;
            #pragma unroll
            for (int nt = 0; nt < 4; nt++) {
                int j0 = nt * 8 + 2 * c;
                float ma0 = maskAdd[j0], ma1 = maskAdd[j0 + 1];
                sc[mt][nt][0] = sc[mt][nt][0] * 0.125f + ma0;
                sc[mt][nt][1] = sc[mt][nt][1] * 0.125f + ma1;
                sc[mt][nt][2] = sc[mt][nt][2] * 0.125f + ma0;
                sc[mt][nt][3] = sc[mt][nt][3] * 0.125f + ma1;
                mxA = fmaxf(mxA, fmaxf(sc[mt][nt][0], sc[mt][nt][1]));
                mxB = fmaxf(mxB, fmaxf(sc[mt][nt][2], sc[mt][nt][3]));
            }
            mxA = fmaxf(mxA, __shfl_xor_sync(0xffffffffu, mxA, 1));
            mxA = fmaxf(mxA, __shfl_xor_sync(0xffffffffu, mxA, 2));
            mxB = fmaxf(mxB, __shfl_xor_sync(0xffffffffu, mxB, 1));
            mxB = fmaxf(mxB, __shfl_xor_sync(0xffffffffu, mxB, 2));

            float mnA = fmaxf(mA[mt], mxA);
            float mnB = fmaxf(mB[mt], mxB);
            float corrA = __expf(mA[mt] - mnA);
            float corrB = __expf(mB[mt] - mnB);
            mA[mt] = mnA; mB[mt] = mnB;

            float psA = 0.f, psB = 0.f;
            #pragma unroll
            for (int nt = 0; nt < 4; nt++) {
                float p0 = __expf(sc[mt][nt][0] - mnA);
                float p1 = __expf(sc[mt][nt][1] - mnA);
                float p2 = __expf(sc[mt][nt][2] - mnB);
                float p3 = __expf(sc[mt][nt][3] - mnB);
                psA += p0 + p1; psB += p2 + p3;
                sc[mt][nt][0] = __uint_as_float(f2tf(p0));
                sc[mt][nt][1] = __uint_as_float(f2tf(p1));
                sc[mt][nt][2] = __uint_as_float(f2tf(p2));
                sc[mt][nt][3] = __uint_as_float(f2tf(p3));
            }
            psA += __shfl_xor_sync(0xffffffffu, psA, 1);
            psA += __shfl_xor_sync(0xffffffffu, psA, 2);
            psB += __shfl_xor_sync(0xffffffffu, psB, 1);
            psB += __shfl_xor_sync(0xffffffffu, psB, 2);
            lA[mt] = lA[mt] * corrA + psA;
            lB[mt] = lB[mt] * corrB + psB;
            #pragma unroll
            for (int nt = 0; nt < 8; nt++) {
                acc[mt][nt][0] *= corrA; acc[mt][nt][1] *= corrA;
                acc[mt][nt][2] *= corrB; acc[mt][nt][3] *= corrB;
            }
        }

        // ---- acc += P @ V (register A-operands, permuted-K V) ----
        #pragma unroll
        for (int ks = 0; ks < 4; ks++) {
            int k0 = ks * 8;
            unsigned aP[2][4];
            #pragma unroll
            for (int mt = 0; mt < 2; mt++) {
                aP[mt][0] = __float_as_uint(sc[mt][ks][0]);
                aP[mt][1] = __float_as_uint(sc[mt][ks][2]);
                aP[mt][2] = __float_as_uint(sc[mt][ks][1]);
                aP[mt][3] = __float_as_uint(sc[mt][ks][3]);
            }
            #pragma unroll
            for (int nt = 0; nt < 8; nt++) {
                int e0 = nt * 8;
                unsigned b0 = Vs[(k0 + c)     * 72 + e0 + g];
                unsigned b1 = Vs[(k0 + 4 + c) * 72 + e0 + g];
                mma_tf32(acc[0][nt], aP[0], b0, b1);
                mma_tf32(acc[1][nt], aP[1], b0, b1);
            }
        }
    }

    // epilogue: store unnormalized acc + (m,l)
    #pragma unroll
    for (int mt = 0; mt < 2; mt++) {
        int rA = row0 + wrow + mt * 16 + g;
        int rB = rA + 8;
        float* obase = Oacc + (size_t)z * MQ * D_;
        #pragma unroll
        for (int nt = 0; nt < 8; nt++) {
            int col = h * E_ + nt * 8 + 2 * c;
            *(float2*)&obase[(size_t)rA * D_ + col] =
                make_float2(acc[mt][nt][0], acc[mt][nt][1]);
            *(float2*)&obase[(size_t)rB * D_ + col] =
                make_float2(acc[mt][nt][2], acc[mt][nt][3]);
        }
        if (c == 0) {
            size_t iA = ((size_t)(z * MQ + rA) * H_ + h) * 2;
            size_t iB = ((size_t)(z * MQ + rB) * H_ + h) * 2;
            ML[iA]     = mA[mt]; ML[iA + 1] = lA[mt];
            ML[iB]     = mB[mt]; ML[iB + 1] = lB[mt];
        }
    }
}

// ---------------------------------------------------------------------------
// Split-KV combine + mean-pool, float4 per thread, per-tq weights hoisted.
// grid: BLn*D_/4/256 = 192 blocks.
// ---------------------------------------------------------------------------
__global__ void combine_pool_kernel(const float* __restrict__ Oacc,
                                    const float* __restrict__ ML,
                                    float* __restrict__ P) {
    int idx4 = blockIdx.x * 256 + threadIdx.x;
    if (idx4 >= BLn * D_ / 4) return;
    int bl = idx4 / (D_ / 4);
    int d  = (idx4 % (D_ / 4)) * 4;
    int h  = d >> 6;
    float4 s4 = make_float4(0.f, 0.f, 0.f, 0.f);
    #pragma unroll
    for (int tq = 0; tq < TQn; tq++) {
        int row = bl * TQn + tq;
        size_t i0 = ((size_t)(0 * MQ + row) * H_ + h) * 2;
        size_t i1 = ((size_t)(1 * MQ + row) * H_ + h) * 2;
        size_t i2 = ((size_t)(2 * MQ + row) * H_ + h) * 2;
        float m0 = ML[i0], l0 = ML[i0 + 1];
        float m1 = ML[i1], l1 = ML[i1 + 1];
        float m2 = ML[i2], l2 = ML[i2 + 1];
        float M = fmaxf(m0, fmaxf(m1, m2));
        float e0 = __expf(m0 - M), e1 = __expf(m1 - M), e2 = __expf(m2 - M);
        float inv = 1.0f / (l0 * e0 + l1 * e1 + l2 * e2);
        float w0 = e0 * inv, w1 = e1 * inv, w2 = e2 * inv;
        float4 a0 = *(const float4*)&Oacc[(size_t)(0 * MQ + row) * D_ + d];
        float4 a1 = *(const float4*)&Oacc[(size_t)(1 * MQ + row) * D_ + d];
        float4 a2 = *(const float4*)&Oacc[(size_t)(2 * MQ + row) * D_ + d];
        s4.x += a0.x * w0 + a1.x * w1 + a2.x * w2;
        s4.y += a0.y * w0 + a1.y * w1 + a2.y * w2;
        s4.z += a0.z * w0 + a1.z * w1 + a2.z * w2;
        s4.w += a0.w * w0 + a1.w * w1 + a2.w * w2;
    }
    s4.x *= (1.0f / TQn); s4.y *= (1.0f / TQn);
    s4.z *= (1.0f / TQn); s4.w *= (1.0f / TQn);
    *(float4*)&P[(size_t)bl * D_ + d] = s4;
}

// ---------------------------------------------------------------------------
extern "C" void kernel_launch(void* const* d_in, const int* in_sizes, int n_in,
                              void* d_out, int out_size) {
    const float* target     = (const float*)d_in[0];
    const float* key_bank   = (const float*)d_in[1];
    const float* value_bank = (const float*)d_in[2];
    const int*   bank_mask  = (const int*)  d_in[3];
    const float* Wq = (const float*)d_in[4];
    const float* bq = (const float*)d_in[5];
    const float* Wk = (const float*)d_in[6];
    const float* bk = (const float*)d_in[7];
    const float* Wv = (const float*)d_in[8];
    const float* bv = (const float*)d_in[9];
    const float* Wo = (const float*)d_in[10];
    const float* bo = (const float*)d_in[11];
    const float* gq = (const float*)d_in[12];
    const float* betaq = (const float*)d_in[13];
    const float* gkv = (const float*)d_in[14];
    const float* betakv = (const float*)d_in[15];
    float* out = (float*)d_out;

    float *Xq, *Xk, *Xv, *Qb, *Kb, *Vb, *Oacc, *ML, *Pool;
    cudaGetSymbolAddress((void**)&Xq,  g_Xq);
    cudaGetSymbolAddress((void**)&Xk,  g_Xk);
    cudaGetSymbolAddress((void**)&Xv,  g_Xv);
    cudaGetSymbolAddress((void**)&Qb,  g_Qb);
    cudaGetSymbolAddress((void**)&Kb,  g_Kb);
    cudaGetSymbolAddress((void**)&Vb,  g_Vb);
    cudaGetSymbolAddress((void**)&Oacc, g_Oacc);
    cudaGetSymbolAddress((void**)&ML,  g_ML);
    cudaGetSymbolAddress((void**)&Pool, g_Pool);

    cudaFuncSetAttribute(attn_tf32,
                         cudaFuncAttributeMaxDynamicSharedMemorySize, ATTN_SMEM);

    // 1. Fused LayerNorms
    ln3_kernel<<<MQ + 2 * S_, 256>>>(target, Xq, gq, betaq,
                                     key_bank, value_bank, Xk, Xv, gkv, betakv);

    // 2. Q/K/V projections (tf32-bit outputs)
    gemm3_tf32<<<dim3(D_ / 128, 16, 3), 256>>>(
        Xq, Wq, bq, Qb, MQ,
        Xk, Wk, bk, Kb, S_,
        Xv, Wv, bv, Vb, S_, 1);

    // 3. Attention: cp.async prefetch, split-KV x3, occ 2, one wave
    attn_tf32<<<dim3(MQ / AQT, H_, NSPLIT), 256, ATTN_SMEM>>>(
        (const unsigned*)Qb, (const unsigned*)Kb, (const unsigned*)Vb,
        bank_mask, Oacc, ML);

    // 4. Combine splits + mean-pool (float4)
    combine_pool_kernel<<<(BLn * D_ / 4 + 255) / 256, 256>>>(Oacc, ML, Pool);

    // 5. Output projection (fp32 out)
    gemm3_tf32<<<dim3(D_ / 128, 2, 1), 256>>>(
        Pool, Wo, bo, out, BLn,
        Pool, Wo, bo, out, BLn,
        Pool, Wo, bo, out, BLn, 0);
}

// round 12
// speedup vs baseline: 1.1193x; 1.0291x over previous
#include <cuda_runtime.h>
#include <math.h>

// Problem constants
#define D_  768
#define H_  12
#define E_  64
#define S_  2000
#define MQ  2048    // B*L*TQ
#define BLn 256     // B*L
#define TQn 8
#define NSPLIT 3

// Scratch (device globals: allocation-free)
__device__ float g_Xq[MQ * D_];
__device__ float g_Xk[S_ * D_];
__device__ float g_Xv[S_ * D_];
__device__ float g_Qb[MQ * D_];               // tf32 bits (gemm cvtOut=1)
__device__ float g_Kb[S_ * D_];               // tf32 bits
__device__ float g_Vb[S_ * D_];               // tf32 bits
__device__ float g_Oacc[NSPLIT * MQ * D_];    // unnormalized per-split attn out
__device__ float g_ML[NSPLIT * MQ * H_ * 2];  // per-split (m, l)
__device__ float g_Pool[BLn * D_];

// ---------------------------------------------------------------------------
// helpers
// ---------------------------------------------------------------------------
__device__ __forceinline__ unsigned f2tf(float x) {
    unsigned r;
    asm("cvt.rna.tf32.f32 %0, %1;" : "=r"(r) : "f"(x));
    return r;
}

__device__ __forceinline__ void mma_tf32(float* d, const unsigned* a,
                                         unsigned b0, unsigned b1) {
    asm volatile(
        "mma.sync.aligned.m16n8k8.row.col.f32.tf32.tf32.f32 "
        "{%0,%1,%2,%3},{%4,%5,%6,%7},{%8,%9},{%0,%1,%2,%3};\n"
        : "+f"(d[0]), "+f"(d[1]), "+f"(d[2]), "+f"(d[3])
        : "r"(a[0]), "r"(a[1]), "r"(a[2]), "r"(a[3]), "r"(b0), "r"(b1));
}

__device__ __forceinline__ void cp16(unsigned* dst_smem, const void* src, bool valid) {
    unsigned daddr = (unsigned)__cvta_generic_to_shared(dst_smem);
    int sz = valid ? 16 : 0;
    asm volatile("cp.async.cg.shared.global [%0], [%1], 16, %2;\n"
                 :: "r"(daddr), "l"(src), "r"(sz));
}
__device__ __forceinline__ void cp_commit() {
    asm volatile("cp.async.commit_group;\n");
}
template <int N>
__device__ __forceinline__ void cp_wait() {
    asm volatile("cp.async.wait_group %0;\n" :: "n"(N));
}

// ---------------------------------------------------------------------------
// Fused LayerNorm: target (2048) + key (2000) + value (2000) in one launch.
// ---------------------------------------------------------------------------
__global__ void ln3_kernel(const float* __restrict__ tgt, float* __restrict__ Xq,
                           const float* __restrict__ gq, const float* __restrict__ bq_,
                           const float* __restrict__ key, const float* __restrict__ val,
                           float* __restrict__ Xk, float* __restrict__ Xv,
                           const float* __restrict__ gkv, const float* __restrict__ bkv) {
    int row = blockIdx.x;
    const float *x, *g, *b;
    float* y;
    if (row < MQ) {
        x = tgt + (size_t)row * D_; y = Xq + (size_t)row * D_; g = gq; b = bq_;
    } else if (row < MQ + S_) {
        int r = row - MQ;
        x = key + (size_t)r * D_; y = Xk + (size_t)r * D_; g = gkv; b = bkv;
    } else {
        int r = row - MQ - S_;
        x = val + (size_t)r * D_; y = Xv + (size_t)r * D_; g = gkv; b = bkv;
    }

    int t = threadIdx.x;
    float v0 = x[t], v1 = x[t + 256], v2 = x[t + 512];
    float s  = v0 + v1 + v2;
    float ss = v0 * v0 + v1 * v1 + v2 * v2;

    __shared__ float redS[8], redQ[8];
    #pragma unroll
    for (int o = 16; o > 0; o >>= 1) {
        s  += __shfl_xor_sync(0xffffffffu, s, o);
        ss += __shfl_xor_sync(0xffffffffu, ss, o);
    }
    int warp = t >> 5, lane = t & 31;
    if (lane == 0) { redS[warp] = s; redQ[warp] = ss; }
    __syncthreads();
    float sum = 0.f, sq = 0.f;
    #pragma unroll
    for (int w = 0; w < 8; w++) { sum += redS[w]; sq += redQ[w]; }

    float mean = sum * (1.0f / D_);
    float var  = sq * (1.0f / D_) - mean * mean;
    float rs   = rsqrtf(var + 1e-5f);

    y[t]       = (v0 - mean) * rs * g[t]       + b[t];
    y[t + 256] = (v1 - mean) * rs * g[t + 256] + b[t + 256];
    y[t + 512] = (v2 - mean) * rs * g[t + 512] + b[t + 512];
}

// ---------------------------------------------------------------------------
// Batched TF32 GEMM (R2/R6 mainloop verbatim): C[M][768] = A @ W^T + bias
// cvtOut=1: store tf32 bit patterns; 0: store fp32.
// ---------------------------------------------------------------------------
__global__ __launch_bounds__(256, 2)
void gemm3_tf32(const float* A0, const float* W0, const float* bi0, float* C0, int M0,
                const float* A1, const float* W1, const float* bi1, float* C1, int M1,
                const float* A2, const float* W2, const float* bi2, float* C2, int M2,
                int cvtOut) {
    const float* A; const float* W; const float* bias; float* C; int M;
    if (blockIdx.z == 0) { A = A0; W = W0; bias = bi0; C = C0; M = M0; }
    else if (blockIdx.z == 1) { A = A1; W = W1; bias = bi1; C = C1; M = M1; }
    else { A = A2; W = W2; bias = bi2; C = C2; M = M2; }

    __shared__ unsigned As[128 * 36];
    __shared__ unsigned Ws[128 * 36];

    int t = threadIdx.x, w = t >> 5, lane = t & 31;
    int g = lane >> 2, c = lane & 3;
    int wm = w >> 2, wn = w & 3;
    int row0 = blockIdx.y * 128;
    int col0 = blockIdx.x * 128;

    float acc[4][4][4];
    #pragma unroll
    for (int i = 0; i < 4; i++)
        #pragma unroll
        for (int j = 0; j < 4; j++)
            #pragma unroll
            for (int k = 0; k < 4; k++) acc[i][j][k] = 0.f;

    for (int k0 = 0; k0 < D_; k0 += 32) {
        __syncthreads();
        #pragma unroll
        for (int i = t; i < 1024; i += 256) {
            int r = i >> 3, kq = (i & 7) << 2;
            int ar = row0 + r;
            float4 av = make_float4(0.f, 0.f, 0.f, 0.f);
            if (ar < M) av = *(const float4*)(A + (size_t)ar * D_ + k0 + kq);
            uint4 ua = make_uint4(f2tf(av.x), f2tf(av.y), f2tf(av.z), f2tf(av.w));
            *(uint4*)&As[r * 36 + kq] = ua;

            float4 wv = *(const float4*)(W + (size_t)(col0 + r) * D_ + k0 + kq);
            uint4 uw = make_uint4(f2tf(wv.x), f2tf(wv.y), f2tf(wv.z), f2tf(wv.w));
            *(uint4*)&Ws[r * 36 + kq] = uw;
        }
        __syncthreads();

        #pragma unroll
        for (int ks = 0; ks < 4; ks++) {
            int kk = ks * 8;
            unsigned a[4][4];
            #pragma unroll
            for (int mt = 0; mt < 4; mt++) {
                int base = wm * 64 + mt * 16;
                a[mt][0] = As[(base + g)     * 36 + kk + c];
                a[mt][1] = As[(base + g + 8) * 36 + kk + c];
                a[mt][2] = As[(base + g)     * 36 + kk + 4 + c];
                a[mt][3] = As[(base + g + 8) * 36 + kk + 4 + c];
            }
            #pragma unroll
            for (int nt = 0; nt < 4; nt++) {
                int n = wn * 32 + nt * 8 + g;
                unsigned b0 = Ws[n * 36 + kk + c];
                unsigned b1 = Ws[n * 36 + kk + 4 + c];
                #pragma unroll
                for (int mt = 0; mt < 4; mt++)
                    mma_tf32(acc[mt][nt], a[mt], b0, b1);
            }
        }
    }

    #pragma unroll
    for (int mt = 0; mt < 4; mt++) {
        int rA = row0 + wm * 64 + mt * 16 + g;
        int rB = rA + 8;
        #pragma unroll
        for (int nt = 0; nt < 4; nt++) {
            int colb = col0 + wn * 32 + nt * 8 + 2 * c;
            float b0v = bias[colb], b1v = bias[colb + 1];
            float v00 = acc[mt][nt][0] + b0v, v01 = acc[mt][nt][1] + b1v;
            float v10 = acc[mt][nt][2] + b0v, v11 = acc[mt][nt][3] + b1v;
            if (cvtOut) {
                v00 = __uint_as_float(f2tf(v00)); v01 = __uint_as_float(f2tf(v01));
                v10 = __uint_as_float(f2tf(v10)); v11 = __uint_as_float(f2tf(v11));
            }
            if (rA < M) {
                C[(size_t)rA * D_ + colb]     = v00;
                C[(size_t)rA * D_ + colb + 1] = v01;
            }
            if (rB < M) {
                C[(size_t)rB * D_ + colb]     = v10;
                C[(size_t)rB * D_ + colb + 1] = v11;
            }
        }
    }
}

// ---------------------------------------------------------------------------
// TF32 flash attention v4b: cp.async double-buffered K/V prefetch, hoisted
// mask, register-P PV (raw fp32 bits as tf32 operands: HW truncates low
// mantissa), ASC=32, occ 2, split-KV x3. grid (8,12,3) = 288 CTAs, one wave.
// ---------------------------------------------------------------------------
#define AQT 256
#define ASC 32
#define NCH ((S_ + ASC - 1) / ASC)              /* 63 */
#define CHSPLIT ((NCH + NSPLIT - 1) / NSPLIT)   /* 21 */
#define KBUF (ASC * 68)
#define VBUF (ASC * 72)
#define ATTN_WORDS (AQT*68 + 2*KBUF + 2*VBUF + CHSPLIT*ASC)
#define ATTN_SMEM  (ATTN_WORDS * 4)

__global__ __launch_bounds__(256, 2)
void attn_tf32(const unsigned* __restrict__ Q, const unsigned* __restrict__ K,
               const unsigned* __restrict__ V, const int* __restrict__ mask,
               float* __restrict__ Oacc, float* __restrict__ ML) {
    extern __shared__ unsigned smu[];
    unsigned* Qs = smu;                        // [256][68]
    unsigned* Ks0 = Qs + AQT * 68;             // 2 x [32][68]
    unsigned* Vs0 = Ks0 + 2 * KBUF;            // 2 x [32][72] rows permuted
    float* maskSm = (float*)(Vs0 + 2 * VBUF);  // [CHSPLIT*32] addends

    int h = blockIdx.y;
    int z = blockIdx.z;
    int row0 = blockIdx.x * AQT;
    int t = threadIdx.x, w = t >> 5, lane = t & 31;
    int g = lane >> 2, c = lane & 3;
    int wrow = w * 32;

    int chBeg = z * CHSPLIT;
    int chEnd = min(chBeg + CHSPLIT, NCH);

    // load Q tile (tf32 bits)
    #pragma unroll 4
    for (int i = t; i < AQT * 16; i += 256) {
        int r = i >> 4, e4 = (i & 15) << 2;
        uint4 q4 = *(const uint4*)(Q + (size_t)(row0 + r) * D_ + h * E_ + e4);
        *(uint4*)&Qs[r * 68 + e4] = q4;
    }
    // hoist mask addends for the whole split
    for (int i = t; i < CHSPLIT * ASC; i += 256) {
        int gs = chBeg * ASC + i;
        maskSm[i] = (gs < S_ && mask[gs] != 0) ? 0.f : -1e30f;
    }

    auto stageKV = [&](int ch, int buf) {
        unsigned* Ks = Ks0 + buf * KBUF;
        unsigned* Vs = Vs0 + buf * VBUF;
        int s0 = ch * ASC;
        #pragma unroll
        for (int i = t; i < ASC * 16; i += 256) {
            int s = i >> 4, e4 = (i & 15) << 2;
            int gs = s0 + s;
            bool ok = gs < S_;
            const unsigned* ksrc = K + (size_t)gs * D_ + h * E_ + e4;
            const unsigned* vsrc = V + (size_t)gs * D_ + h * E_ + e4;
            cp16(&Ks[s * 68 + e4], ksrc, ok);
            int sw = s & 7;
            int sp = (s & ~7) | ((sw & 1) ? 4 + (sw >> 1) : (sw >> 1));
            cp16(&Vs[sp * 72 + e4], vsrc, ok);
        }
        cp_commit();
    };

    float mA[2] = {-1e30f, -1e30f}, mB[2] = {-1e30f, -1e30f};
    float lA[2] = {0.f, 0.f}, lB[2] = {0.f, 0.f};
    float acc[2][8][4];
    #pragma unroll
    for (int mt = 0; mt < 2; mt++)
        #pragma unroll
        for (int nt = 0; nt < 8; nt++)
            #pragma unroll
            for (int k = 0; k < 4; k++) acc[mt][nt][k] = 0.f;

    stageKV(chBeg, 0);

    for (int ch = chBeg; ch < chEnd; ch++) {
        int buf = (ch - chBeg) & 1;
        __syncthreads();   // guard: prior readers of buf^1 done
        if (ch + 1 < chEnd) {
            stageKV(ch + 1, buf ^ 1);
            cp_wait<1>();
        } else {
            cp_wait<0>();
        }
        __syncthreads();   // staged data visible

        const unsigned* Ks = Ks0 + buf * KBUF;
        const unsigned* Vs = Vs0 + buf * VBUF;
        const float* maskAdd = maskSm + (ch - chBeg) * ASC;

        // ---- scores = Q @ K^T  (32 cols) ----
        float sc[2][4][4];
        #pragma unroll
        for (int mt = 0; mt < 2; mt++)
            #pragma unroll
            for (int nt = 0; nt < 4; nt++)
                #pragma unroll
                for (int k = 0; k < 4; k++) sc[mt][nt][k] = 0.f;

        #pragma unroll
        for (int ks = 0; ks < 8; ks++) {
            int k0 = ks * 8;
            unsigned a[2][4];
            #pragma unroll
            for (int mt = 0; mt < 2; mt++) {
                int base = wrow + mt * 16;
                a[mt][0] = Qs[(base + g)     * 68 + k0 + c];
                a[mt][1] = Qs[(base + g + 8) * 68 + k0 + c];
                a[mt][2] = Qs[(base + g)     * 68 + k0 + 4 + c];
                a[mt][3] = Qs[(base + g + 8) * 68 + k0 + 4 + c];
            }
            #pragma unroll
            for (int nt = 0; nt < 4; nt++) {
                int n0 = nt * 8;
                unsigned b0 = Ks[(n0 + g) * 68 + k0 + c];
                unsigned b1 = Ks[(n0 + g) * 68 + k0 + 4 + c];
                mma_tf32(sc[0][nt], a[0], b0, b1);
                mma_tf32(sc[1][nt], a[1], b0, b1);
            }
        }

        // ---- online softmax; exp'd P kept raw in registers ----
        #pragma unroll
        for (int mt = 0; mt < 2; mt++) {
            float mxA = -1e30f, mxB = -1e30f;
            #pragma unroll
            for (int nt = 0; nt < 4; nt++) {
                int j0 = nt * 8 + 2 * c;
                float ma0 = maskAdd[j0], ma1 = maskAdd[j0 + 1];
                sc[mt][nt][0] = sc[mt][nt][0] * 0.125f + ma0;
                sc[mt][nt][1] = sc[mt][nt][1] * 0.125f + ma1;
                sc[mt][nt][2] = sc[mt][nt][2] * 0.125f + ma0;
                sc[mt][nt][3] = sc[mt][nt][3] * 0.125f + ma1;
                mxA = fmaxf(mxA, fmaxf(sc[mt][nt][0], sc[mt][nt][1]));
                mxB = fmaxf(mxB, fmaxf(sc[mt][nt][2], sc[mt][nt][3]));
            }
            mxA = fmaxf(mxA, __shfl_xor_sync(0xffffffffu, mxA, 1));
            mxA = fmaxf(mxA, __shfl_xor_sync(0xffffffffu, mxA, 2));
            mxB = fmaxf(mxB, __shfl_xor_sync(0xffffffffu, mxB, 1));
            mxB = fmaxf(mxB, __shfl_xor_sync(0xffffffffu, mxB, 2));

            float mnA = fmaxf(mA[mt], mxA);
            float mnB = fmaxf(mB[mt], mxB);
            float corrA = __expf(mA[mt] - mnA);
            float corrB = __expf(mB[mt] - mnB);
            mA[mt] = mnA; mB[mt] = mnB;

            float psA = 0.f, psB = 0.f;
            #pragma unroll
            for (int nt = 0; nt < 4; nt++) {
                float p0 = __expf(sc[mt][nt][0] - mnA);
                float p1 = __expf(sc[mt][nt][1] - mnA);
                float p2 = __expf(sc[mt][nt][2] - mnB);
                float p3 = __expf(sc[mt][nt][3] - mnB);
                psA += p0 + p1; psB += p2 + p3;
                // store raw fp32 bits; tf32 mma truncates low mantissa in HW
                sc[mt][nt][0] = p0;
                sc[mt][nt][1] = p1;
                sc[mt][nt][2] = p2;
                sc[mt][nt][3] = p3;
            }
            psA += __shfl_xor_sync(0xffffffffu, psA, 1);
            psA += __shfl_xor_sync(0xffffffffu, psA, 2);
            psB += __shfl_xor_sync(0xffffffffu, psB, 1);
            psB += __shfl_xor_sync(0xffffffffu, psB, 2);
            lA[mt] = lA[mt] * corrA + psA;
            lB[mt] = lB[mt] * corrB + psB;
            #pragma unroll
            for (int nt = 0; nt < 8; nt++) {
                acc[mt][nt][0] *= corrA; acc[mt][nt][1] *= corrA;
                acc[mt][nt][2] *= corrB; acc[mt][nt][3] *= corrB;
            }
        }

        // ---- acc += P @ V (register A-operands, permuted-K V) ----
        #pragma unroll
        for (int ks = 0; ks < 4; ks++) {
            int k0 = ks * 8;
            unsigned aP[2][4];
            #pragma unroll
            for (int mt = 0; mt < 2; mt++) {
                aP[mt][0] = __float_as_uint(sc[mt][ks][0]);
                aP[mt][1] = __float_as_uint(sc[mt][ks][2]);
                aP[mt][2] = __float_as_uint(sc[mt][ks][1]);
                aP[mt][3] = __float_as_uint(sc[mt][ks][3]);
            }
            #pragma unroll
            for (int nt = 0; nt < 8; nt++) {
                int e0 = nt * 8;
                unsigned b0 = Vs[(k0 + c)     * 72 + e0 + g];
                unsigned b1 = Vs[(k0 + 4 + c) * 72 + e0 + g];
                mma_tf32(acc[0][nt], aP[0], b0, b1);
                mma_tf32(acc[1][nt], aP[1], b0, b1);
            }
        }
    }

    // epilogue: store unnormalized acc + (m,l)
    #pragma unroll
    for (int mt = 0; mt < 2; mt++) {
        int rA = row0 + wrow + mt * 16 + g;
        int rB = rA + 8;
        float* obase = Oacc + (size_t)z * MQ * D_;
        #pragma unroll
        for (int nt = 0; nt < 8; nt++) {
            int col = h * E_ + nt * 8 + 2 * c;
            *(float2*)&obase[(size_t)rA * D_ + col] =
                make_float2(acc[mt][nt][0], acc[mt][nt][1]);
            *(float2*)&obase[(size_t)rB * D_ + col] =
                make_float2(acc[mt][nt][2], acc[mt][nt][3]);
        }
        if (c == 0) {
            size_t iA = ((size_t)(z * MQ + rA) * H_ + h) * 2;
            size_t iB = ((size_t)(z * MQ + rB) * H_ + h) * 2;
            ML[iA]     = mA[mt]; ML[iA + 1] = lA[mt];
            ML[iB]     = mB[mt]; ML[iB + 1] = lB[mt];
        }
    }
}

// ---------------------------------------------------------------------------
// Split-KV combine + mean-pool over TQ=8 (R9 scalar form, 768 blocks)
// ---------------------------------------------------------------------------
__global__ void combine_pool_kernel(const float* __restrict__ Oacc,
                                    const float* __restrict__ ML,
                                    float* __restrict__ P) {
    int idx = blockIdx.x * 256 + threadIdx.x;
    if (idx >= BLn * D_) return;
    int bl = idx / D_, d = idx % D_;
    int h = d >> 6;
    float s = 0.f;
    #pragma unroll
    for (int tq = 0; tq < TQn; tq++) {
        int row = bl * TQn + tq;
        size_t i0 = ((size_t)(0 * MQ + row) * H_ + h) * 2;
        size_t i1 = ((size_t)(1 * MQ + row) * H_ + h) * 2;
        size_t i2 = ((size_t)(2 * MQ + row) * H_ + h) * 2;
        float m0 = ML[i0], l0 = ML[i0 + 1];
        float m1 = ML[i1], l1 = ML[i1 + 1];
        float m2 = ML[i2], l2 = ML[i2 + 1];
        float M = fmaxf(m0, fmaxf(m1, m2));
        float w0 = __expf(m0 - M), w1 = __expf(m1 - M), w2 = __expf(m2 - M);
        float denom = l0 * w0 + l1 * w1 + l2 * w2;
        float a0 = Oacc[(size_t)(0 * MQ + row) * D_ + d];
        float a1 = Oacc[(size_t)(1 * MQ + row) * D_ + d];
        float a2 = Oacc[(size_t)(2 * MQ + row) * D_ + d];
        s += (a0 * w0 + a1 * w1 + a2 * w2) / denom;
    }
    P[idx] = s * (1.0f / TQn);
}

// ---------------------------------------------------------------------------
extern "C" void kernel_launch(void* const* d_in, const int* in_sizes, int n_in,
                              void* d_out, int out_size) {
    const float* target     = (const float*)d_in[0];
    const float* key_bank   = (const float*)d_in[1];
    const float* value_bank = (const float*)d_in[2];
    const int*   bank_mask  = (const int*)  d_in[3];
    const float* Wq = (const float*)d_in[4];
    const float* bq = (const float*)d_in[5];
    const float* Wk = (const float*)d_in[6];
    const float* bk = (const float*)d_in[7];
    const float* Wv = (const float*)d_in[8];
    const float* bv = (const float*)d_in[9];
    const float* Wo = (const float*)d_in[10];
    const float* bo = (const float*)d_in[11];
    const float* gq = (const float*)d_in[12];
    const float* betaq = (const float*)d_in[13];
    const float* gkv = (const float*)d_in[14];
    const float* betakv = (const float*)d_in[15];
    float* out = (float*)d_out;

    float *Xq, *Xk, *Xv, *Qb, *Kb, *Vb, *Oacc, *ML, *Pool;
    cudaGetSymbolAddress((void**)&Xq,  g_Xq);
    cudaGetSymbolAddress((void**)&Xk,  g_Xk);
    cudaGetSymbolAddress((void**)&Xv,  g_Xv);
    cudaGetSymbolAddress((void**)&Qb,  g_Qb);
    cudaGetSymbolAddress((void**)&Kb,  g_Kb);
    cudaGetSymbolAddress((void**)&Vb,  g_Vb);
    cudaGetSymbolAddress((void**)&Oacc, g_Oacc);
    cudaGetSymbolAddress((void**)&ML,  g_ML);
    cudaGetSymbolAddress((void**)&Pool, g_Pool);

    cudaFuncSetAttribute(attn_tf32,
                         cudaFuncAttributeMaxDynamicSharedMemorySize, ATTN_SMEM);

    // 1. Fused LayerNorms
    ln3_kernel<<<MQ + 2 * S_, 256>>>(target, Xq, gq, betaq,
                                     key_bank, value_bank, Xk, Xv, gkv, betakv);

    // 2. Q/K/V projections (tf32-bit outputs)
    gemm3_tf32<<<dim3(D_ / 128, 16, 3), 256>>>(
        Xq, Wq, bq, Qb, MQ,
        Xk, Wk, bk, Kb, S_,
        Xv, Wv, bv, Vb, S_, 1);

    // 3. Attention: cp.async prefetch, split-KV x3, occ 2, one wave
    attn_tf32<<<dim3(MQ / AQT, H_, NSPLIT), 256, ATTN_SMEM>>>(
        (const unsigned*)Qb, (const unsigned*)Kb, (const unsigned*)Vb,
        bank_mask, Oacc, ML);

    // 4. Combine splits + mean-pool (scalar, 768 blocks)
    combine_pool_kernel<<<(BLn * D_ + 255) / 256, 256>>>(Oacc, ML, Pool);

    // 5. Output projection (fp32 out)
    gemm3_tf32<<<dim3(D_ / 128, 2, 1), 256>>>(
        Pool, Wo, bo, out, BLn,
        Pool, Wo, bo, out, BLn,
        Pool, Wo, bo, out, BLn, 0);
}

// round 13
// speedup vs baseline: 1.5722x; 1.4046x over previous
#include <cuda_runtime.h>
#include <cuda_fp16.h>
#include <math.h>

// Problem constants
#define D_  768
#define H_  12
#define E_  64
#define S_  2000
#define MQ  2048
#define BLn 256
#define TQn 8
#define NSPLIT 3

// Scratch (device globals)
__device__ __half g_Xq[MQ * D_];
__device__ __half g_Xk[S_ * D_];
__device__ __half g_Xv[S_ * D_];
__device__ __half g_Qb[MQ * D_];
__device__ __half g_Kb[S_ * D_];
__device__ __half g_Vb[S_ * D_];
__device__ float  g_Oacc[NSPLIT * MQ * D_];
__device__ float  g_ML[NSPLIT * MQ * H_ * 2];
__device__ __half g_Pool[BLn * D_];

// ---------------------------------------------------------------------------
// helpers
// ---------------------------------------------------------------------------
__device__ __forceinline__ void mma_f16(float* d, const unsigned* a,
                                        unsigned b0, unsigned b1) {
    asm volatile(
        "mma.sync.aligned.m16n8k16.row.col.f32.f16.f16.f32 "
        "{%0,%1,%2,%3},{%4,%5,%6,%7},{%8,%9},{%0,%1,%2,%3};\n"
        : "+f"(d[0]), "+f"(d[1]), "+f"(d[2]), "+f"(d[3])
        : "r"(a[0]), "r"(a[1]), "r"(a[2]), "r"(a[3]), "r"(b0), "r"(b1));
}

__device__ __forceinline__ unsigned packh2(float x, float y) {
    __half2 h = __floats2half2_rn(x, y);
    return *reinterpret_cast<unsigned*>(&h);
}

__device__ __forceinline__ void cp8(unsigned* dst_smem, const void* src, bool valid) {
    unsigned d = (unsigned)__cvta_generic_to_shared(dst_smem);
    int sz = valid ? 8 : 0;
    asm volatile("cp.async.ca.shared.global [%0], [%1], 8, %2;\n"
                 :: "r"(d), "l"(src), "r"(sz));
}
__device__ __forceinline__ void cp_commit() {
    asm volatile("cp.async.commit_group;\n");
}
template <int N>
__device__ __forceinline__ void cp_wait() {
    asm volatile("cp.async.wait_group %0;\n" :: "n"(N));
}

// ---------------------------------------------------------------------------
// Fused LayerNorm -> half outputs
// ---------------------------------------------------------------------------
__global__ void ln3_kernel(const float* __restrict__ tgt, __half* __restrict__ Xq,
                           const float* __restrict__ gq, const float* __restrict__ bq_,
                           const float* __restrict__ key, const float* __restrict__ val,
                           __half* __restrict__ Xk, __half* __restrict__ Xv,
                           const float* __restrict__ gkv, const float* __restrict__ bkv) {
    int row = blockIdx.x;
    const float *x, *g, *b;
    __half* y;
    if (row < MQ) {
        x = tgt + (size_t)row * D_; y = Xq + (size_t)row * D_; g = gq; b = bq_;
    } else if (row < MQ + S_) {
        int r = row - MQ;
        x = key + (size_t)r * D_; y = Xk + (size_t)r * D_; g = gkv; b = bkv;
    } else {
        int r = row - MQ - S_;
        x = val + (size_t)r * D_; y = Xv + (size_t)r * D_; g = gkv; b = bkv;
    }

    int t = threadIdx.x;
    float v0 = x[t], v1 = x[t + 256], v2 = x[t + 512];
    float s  = v0 + v1 + v2;
    float ss = v0 * v0 + v1 * v1 + v2 * v2;

    __shared__ float redS[8], redQ[8];
    #pragma unroll
    for (int o = 16; o > 0; o >>= 1) {
        s  += __shfl_xor_sync(0xffffffffu, s, o);
        ss += __shfl_xor_sync(0xffffffffu, ss, o);
    }
    int warp = t >> 5, lane = t & 31;
    if (lane == 0) { redS[warp] = s; redQ[warp] = ss; }
    __syncthreads();
    float sum = 0.f, sq = 0.f;
    #pragma unroll
    for (int w = 0; w < 8; w++) { sum += redS[w]; sq += redQ[w]; }

    float mean = sum * (1.0f / D_);
    float var  = sq * (1.0f / D_) - mean * mean;
    float rs   = rsqrtf(var + 1e-5f);

    y[t]       = __float2half_rn((v0 - mean) * rs * g[t]       + b[t]);
    y[t + 256] = __float2half_rn((v1 - mean) * rs * g[t + 256] + b[t + 256]);
    y[t + 512] = __float2half_rn((v2 - mean) * rs * g[t + 512] + b[t + 512]);
}

// ---------------------------------------------------------------------------
// Batched FP16 GEMM: C[M][768] = A(half) @ W(fp32)^T + bias
// 128x128 tile, BK=32, 256 threads, warp tile 64x32; m16n8k16 fp16 mma.
// As/Ws: half2 rows, stride 20 words (conflict-free quad reads).
// cvtOut=1 -> half output; 0 -> fp32 output.
// ---------------------------------------------------------------------------
#define GST 20
__global__ __launch_bounds__(256, 2)
void gemm3_f16(const __half* A0, const float* W0, const float* bi0, void* C0, int M0,
               const __half* A1, const float* W1, const float* bi1, void* C1, int M1,
               const __half* A2, const float* W2, const float* bi2, void* C2, int M2,
               int cvtOut) {
    const __half* A; const float* W; const float* bias; void* C; int M;
    if (blockIdx.z == 0) { A = A0; W = W0; bias = bi0; C = C0; M = M0; }
    else if (blockIdx.z == 1) { A = A1; W = W1; bias = bi1; C = C1; M = M1; }
    else { A = A2; W = W2; bias = bi2; C = C2; M = M2; }

    __shared__ unsigned As[128 * GST];   // half2 words
    __shared__ unsigned Ws[128 * GST];

    int t = threadIdx.x, w = t >> 5, lane = t & 31;
    int g = lane >> 2, c = lane & 3;
    int wm = w >> 2, wn = w & 3;
    int row0 = blockIdx.y * 128;
    int col0 = blockIdx.x * 128;

    float acc[4][4][4];
    #pragma unroll
    for (int i = 0; i < 4; i++)
        #pragma unroll
        for (int j = 0; j < 4; j++)
            #pragma unroll
            for (int k = 0; k < 4; k++) acc[i][j][k] = 0.f;

    for (int k0 = 0; k0 < D_; k0 += 32) {
        __syncthreads();
        // A: 128 rows x 32 halves; 512 uint4 items
        #pragma unroll
        for (int i = t; i < 512; i += 256) {
            int r = i >> 2, ch = i & 3;
            int ar = row0 + r;
            uint4 av = make_uint4(0u, 0u, 0u, 0u);
            if (ar < M) av = *(const uint4*)(A + (size_t)ar * D_ + k0 + ch * 8);
            unsigned* dst = &As[r * GST + ch * 4];
            *(uint2*)dst       = make_uint2(av.x, av.y);
            *(uint2*)(dst + 2) = make_uint2(av.z, av.w);
        }
        // W: 128 rows x 32 floats -> half2; 1024 float4 items
        #pragma unroll
        for (int i = t; i < 1024; i += 256) {
            int r = i >> 3, q = i & 7;
            float4 wv = *(const float4*)(W + (size_t)(col0 + r) * D_ + k0 + q * 4);
            *(uint2*)&Ws[r * GST + q * 2] =
                make_uint2(packh2(wv.x, wv.y), packh2(wv.z, wv.w));
        }
        __syncthreads();

        #pragma unroll
        for (int ks = 0; ks < 2; ks++) {
            int kk = ks * 8;
            unsigned a[4][4];
            #pragma unroll
            for (int mt = 0; mt < 4; mt++) {
                int base = wm * 64 + mt * 16;
                a[mt][0] = As[(base + g)     * GST + kk + c];
                a[mt][1] = As[(base + g + 8) * GST + kk + c];
                a[mt][2] = As[(base + g)     * GST + kk + 4 + c];
                a[mt][3] = As[(base + g + 8) * GST + kk + 4 + c];
            }
            #pragma unroll
            for (int nt = 0; nt < 4; nt++) {
                int n = wn * 32 + nt * 8 + g;
                unsigned b0 = Ws[n * GST + kk + c];
                unsigned b1 = Ws[n * GST + kk + 4 + c];
                #pragma unroll
                for (int mt = 0; mt < 4; mt++)
                    mma_f16(acc[mt][nt], a[mt], b0, b1);
            }
        }
    }

    #pragma unroll
    for (int mt = 0; mt < 4; mt++) {
        int rA = row0 + wm * 64 + mt * 16 + g;
        int rB = rA + 8;
        #pragma unroll
        for (int nt = 0; nt < 4; nt++) {
            int colb = col0 + wn * 32 + nt * 8 + 2 * c;
            float b0v = bias[colb], b1v = bias[colb + 1];
            float v00 = acc[mt][nt][0] + b0v, v01 = acc[mt][nt][1] + b1v;
            float v10 = acc[mt][nt][2] + b0v, v11 = acc[mt][nt][3] + b1v;
            if (cvtOut) {
                __half* Ch = (__half*)C;
                if (rA < M) *(unsigned*)&Ch[(size_t)rA * D_ + colb] = packh2(v00, v01);
                if (rB < M) *(unsigned*)&Ch[(size_t)rB * D_ + colb] = packh2(v10, v11);
            } else {
                float* Cf = (float*)C;
                if (rA < M) *(float2*)&Cf[(size_t)rA * D_ + colb] = make_float2(v00, v01);
                if (rB < M) *(float2*)&Cf[(size_t)rB * D_ + colb] = make_float2(v10, v11);
            }
        }
    }
}

// ---------------------------------------------------------------------------
// FP16 flash attention: m16n8k16, register-P PV (natural pack), transposed V
// (lane-major staging, conflict-free), pipelined K(cp.async)+V(reg) prefetch,
// hoisted mask, ASC=32, split-KV x3. grid (8,12,3) = 288 CTAs, one wave.
// Layout: Qs/Ks stride 36 words (half2), Vt [e][s] stride 20 words.
// ---------------------------------------------------------------------------
#define AQT 256
#define ASC 32
#define NCH ((S_ + ASC - 1) / ASC)
#define CHSPLIT ((NCH + NSPLIT - 1) / NSPLIT)
#define QST 36
#define KST 36
#define VST 20
#define KBUF (ASC * KST)
#define VBUF (E_ * VST)
#define ATTN_WORDS (AQT*QST + 2*KBUF + 2*VBUF + CHSPLIT*ASC)
#define ATTN_SMEM  (ATTN_WORDS * 4)

__global__ __launch_bounds__(256, 2)
void attn_f16(const __half* __restrict__ Q, const __half* __restrict__ K,
              const __half* __restrict__ V, const int* __restrict__ mask,
              float* __restrict__ Oacc, float* __restrict__ ML) {
    extern __shared__ unsigned smu[];
    unsigned* Qs = smu;                        // [256][36]
    unsigned* Ks0 = Qs + AQT * QST;            // 2 x [32][36]
    unsigned* Vt0 = Ks0 + 2 * KBUF;            // 2 x [64 e][20]
    float* maskSm = (float*)(Vt0 + 2 * VBUF);  // [CHSPLIT*32]

    int h = blockIdx.y;
    int z = blockIdx.z;
    int row0 = blockIdx.x * AQT;
    int t = threadIdx.x, w = t >> 5, lane = t & 31;
    int g = lane >> 2, c = lane & 3;
    int wrow = w * 32;

    int chBeg = z * CHSPLIT;
    int chEnd = min(chBeg + CHSPLIT, NCH);

    // Q tile: 256 rows x 64 halves; 2048 uint4 items
    #pragma unroll 4
    for (int i = t; i < AQT * 8; i += 256) {
        int r = i >> 3, part = i & 7;
        uint4 q4 = *(const uint4*)(Q + (size_t)(row0 + r) * D_ + h * E_ + part * 8);
        *(uint4*)&Qs[r * QST + part * 4] = q4;
    }
    for (int i = t; i < CHSPLIT * ASC; i += 256) {
        int gs = chBeg * ASC + i;
        maskSm[i] = (gs < S_ && mask[gs] != 0) ? 0.f : -1e30f;
    }

    // K staging via cp.async (8B), 512 items
    auto stageK = [&](int ch, int buf) {
        unsigned* Ks = Ks0 + buf * KBUF;
        int s0 = ch * ASC;
        #pragma unroll
        for (int i = t; i < ASC * 16; i += 256) {
            int s = i >> 4, chk = i & 15;
            int gs = s0 + s;
            cp8(&Ks[s * KST + chk * 2],
                K + (size_t)gs * D_ + h * E_ + chk * 4, gs < S_);
        }
        cp_commit();
    };
    // V load into registers (lane-major s): w=part, lane=s
    auto loadV = [&](int ch) -> uint4 {
        int gs = ch * ASC + lane;
        if (gs < S_)
            return *(const uint4*)(V + (size_t)gs * D_ + h * E_ + w * 8);
        return make_uint4(0u, 0u, 0u, 0u);
    };
    auto storeV = [&](uint4 v, int buf) {
        __half* Vth = (__half*)(Vt0 + buf * VBUF);
        const __half* hv = (const __half*)&v;
        #pragma unroll
        for (int j = 0; j < 8; j++)
            Vth[(w * 8 + j) * (VST * 2) + lane] = hv[j];
    };

    float mA[2] = {-1e30f, -1e30f}, mB[2] = {-1e30f, -1e30f};
    float lA[2] = {0.f, 0.f}, lB[2] = {0.f, 0.f};
    float acc[2][8][4];
    #pragma unroll
    for (int mt = 0; mt < 2; mt++)
        #pragma unroll
        for (int nt = 0; nt < 8; nt++)
            #pragma unroll
            for (int k = 0; k < 4; k++) acc[mt][nt][k] = 0.f;

    // prologue: fully stage chunk chBeg into buf 0
    {
        uint4 v0 = loadV(chBeg);
        stageK(chBeg, 0);
        cp_wait<0>();
        storeV(v0, 0);
    }
    __syncthreads();

    for (int ch = chBeg; ch < chEnd; ch++) {
        int buf = (ch - chBeg) & 1;
        bool more = (ch + 1 < chEnd);
        uint4 vnext;
        if (more) {
            vnext = loadV(ch + 1);
            stageK(ch + 1, buf ^ 1);
        }

        const unsigned* Ks = Ks0 + buf * KBUF;
        const unsigned* Vt = Vt0 + buf * VBUF;
        const float* maskAdd = maskSm + (ch - chBeg) * ASC;

        // ---- scores = Q @ K^T (32 cols), 4 k-steps of 16 ----
        float sc[2][4][4];
        #pragma unroll
        for (int mt = 0; mt < 2; mt++)
            #pragma unroll
            for (int nt = 0; nt < 4; nt++)
                #pragma unroll
                for (int k = 0; k < 4; k++) sc[mt][nt][k] = 0.f;

        #pragma unroll
        for (int ks = 0; ks < 4; ks++) {
            int kk = ks * 8;
            unsigned a[2][4];
            #pragma unroll
            for (int mt = 0; mt < 2; mt++) {
                int base = wrow + mt * 16;
                a[mt][0] = Qs[(base + g)     * QST + kk + c];
                a[mt][1] = Qs[(base + g + 8) * QST + kk + c];
                a[mt][2] = Qs[(base + g)     * QST + kk + 4 + c];
                a[mt][3] = Qs[(base + g + 8) * QST + kk + 4 + c];
            }
            #pragma unroll
            for (int nt = 0; nt < 4; nt++) {
                int n0 = nt * 8;
                unsigned b0 = Ks[(n0 + g) * KST + kk + c];
                unsigned b1 = Ks[(n0 + g) * KST + kk + 4 + c];
                mma_f16(sc[0][nt], a[0], b0, b1);
                mma_f16(sc[1][nt], a[1], b0, b1);
            }
        }

        // ---- online softmax (p stays raw fp32 in sc) ----
        #pragma unroll
        for (int mt = 0; mt < 2; mt++) {
            float mxA = -1e30f, mxB = -1e30f;
            #pragma unroll
            for (int nt = 0; nt < 4; nt++) {
                int j0 = nt * 8 + 2 * c;
                float ma0 = maskAdd[j0], ma1 = maskAdd[j0 + 1];
                sc[mt][nt][0] = sc[mt][nt][0] * 0.125f + ma0;
                sc[mt][nt][1] = sc[mt][nt][1] * 0.125f + ma1;
                sc[mt][nt][2] = sc[mt][nt][2] * 0.125f + ma0;
                sc[mt][nt][3] = sc[mt][nt][3] * 0.125f + ma1;
                mxA = fmaxf(mxA, fmaxf(sc[mt][nt][0], sc[mt][nt][1]));
                mxB = fmaxf(mxB, fmaxf(sc[mt][nt][2], sc[mt][nt][3]));
            }
            mxA = fmaxf(mxA, __shfl_xor_sync(0xffffffffu, mxA, 1));
            mxA = fmaxf(mxA, __shfl_xor_sync(0xffffffffu, mxA, 2));
            mxB = fmaxf(mxB, __shfl_xor_sync(0xffffffffu, mxB, 1));
            mxB = fmaxf(mxB, __shfl_xor_sync(0xffffffffu, mxB, 2));

            float mnA = fmaxf(mA[mt], mxA);
            float mnB = fmaxf(mB[mt], mxB);
            float corrA = __expf(mA[mt] - mnA);
            float corrB = __expf(mB[mt] - mnB);
            mA[mt] = mnA; mB[mt] = mnB;

            float psA = 0.f, psB = 0.f;
            #pragma unroll
            for (int nt = 0; nt < 4; nt++) {
                float p0 = __expf(sc[mt][nt][0] - mnA);
                float p1 = __expf(sc[mt][nt][1] - mnA);
                float p2 = __expf(sc[mt][nt][2] - mnB);
                float p3 = __expf(sc[mt][nt][3] - mnB);
                psA += p0 + p1; psB += p2 + p3;
                sc[mt][nt][0] = p0; sc[mt][nt][1] = p1;
                sc[mt][nt][2] = p2; sc[mt][nt][3] = p3;
            }
            psA += __shfl_xor_sync(0xffffffffu, psA, 1);
            psA += __shfl_xor_sync(0xffffffffu, psA, 2);
            psB += __shfl_xor_sync(0xffffffffu, psB, 1);
            psB += __shfl_xor_sync(0xffffffffu, psB, 2);
            lA[mt] = lA[mt] * corrA + psA;
            lB[mt] = lB[mt] * corrB + psB;
            #pragma unroll
            for (int nt = 0; nt < 8; nt++) {
                acc[mt][nt][0] *= corrA; acc[mt][nt][1] *= corrA;
                acc[mt][nt][2] *= corrB; acc[mt][nt][3] *= corrB;
            }
        }

        // ---- acc += P @ V : 2 k-steps of 16; A packed from sc directly ----
        #pragma unroll
        for (int ks = 0; ks < 2; ks++) {
            int kk = ks * 8;
            int t0 = ks * 2, t1 = t0 + 1;
            unsigned aP[2][4];
            #pragma unroll
            for (int mt = 0; mt < 2; mt++) {
                aP[mt][0] = packh2(sc[mt][t0][0], sc[mt][t0][1]);
                aP[mt][1] = packh2(sc[mt][t0][2], sc[mt][t0][3]);
                aP[mt][2] = packh2(sc[mt][t1][0], sc[mt][t1][1]);
                aP[mt][3] = packh2(sc[mt][t1][2], sc[mt][t1][3]);
            }
            #pragma unroll
            for (int nt = 0; nt < 8; nt++) {
                int e0 = nt * 8;
                unsigned b0 = Vt[(e0 + g) * VST + kk + c];
                unsigned b1 = Vt[(e0 + g) * VST + kk + 4 + c];
                mma_f16(acc[0][nt], aP[0], b0, b1);
                mma_f16(acc[1][nt], aP[1], b0, b1);
            }
        }

        if (more) {
            cp_wait<0>();
            storeV(vnext, buf ^ 1);
        }
        __syncthreads();
    }

    // epilogue: unnormalized acc + (m,l)
    #pragma unroll
    for (int mt = 0; mt < 2; mt++) {
        int rA = row0 + wrow + mt * 16 + g;
        int rB = rA + 8;
        float* obase = Oacc + (size_t)z * MQ * D_;
        #pragma unroll
        for (int nt = 0; nt < 8; nt++) {
            int col = h * E_ + nt * 8 + 2 * c;
            *(float2*)&obase[(size_t)rA * D_ + col] =
                make_float2(acc[mt][nt][0], acc[mt][nt][1]);
            *(float2*)&obase[(size_t)rB * D_ + col] =
                make_float2(acc[mt][nt][2], acc[mt][nt][3]);
        }
        if (c == 0) {
            size_t iA = ((size_t)(z * MQ + rA) * H_ + h) * 2;
            size_t iB = ((size_t)(z * MQ + rB) * H_ + h) * 2;
            ML[iA]     = mA[mt]; ML[iA + 1] = lA[mt];
            ML[iB]     = mB[mt]; ML[iB + 1] = lB[mt];
        }
    }
}

// ---------------------------------------------------------------------------
// Split-KV combine + mean-pool (scalar, 768 blocks); half output
// ---------------------------------------------------------------------------
__global__ void combine_pool_kernel(const float* __restrict__ Oacc,
                                    const float* __restrict__ ML,
                                    __half* __restrict__ P) {
    int idx = blockIdx.x * 256 + threadIdx.x;
    if (idx >= BLn * D_) return;
    int bl = idx / D_, d = idx % D_;
    int h = d >> 6;
    float s = 0.f;
    #pragma unroll
    for (int tq = 0; tq < TQn; tq++) {
        int row = bl * TQn + tq;
        size_t i0 = ((size_t)(0 * MQ + row) * H_ + h) * 2;
        size_t i1 = ((size_t)(1 * MQ + row) * H_ + h) * 2;
        size_t i2 = ((size_t)(2 * MQ + row) * H_ + h) * 2;
        float m0 = ML[i0], l0 = ML[i0 + 1];
        float m1 = ML[i1], l1 = ML[i1 + 1];
        float m2 = ML[i2], l2 = ML[i2 + 1];
        float M = fmaxf(m0, fmaxf(m1, m2));
        float w0 = __expf(m0 - M), w1 = __expf(m1 - M), w2 = __expf(m2 - M);
        float denom = l0 * w0 + l1 * w1 + l2 * w2;
        float a0 = Oacc[(size_t)(0 * MQ + row) * D_ + d];
        float a1 = Oacc[(size_t)(1 * MQ + row) * D_ + d];
        float a2 = Oacc[(size_t)(2 * MQ + row) * D_ + d];
        s += (a0 * w0 + a1 * w1 + a2 * w2) / denom;
    }
    P[idx] = __float2half_rn(s * (1.0f / TQn));
}

// ---------------------------------------------------------------------------
extern "C" void kernel_launch(void* const* d_in, const int* in_sizes, int n_in,
                              void* d_out, int out_size) {
    const float* target     = (const float*)d_in[0];
    const float* key_bank   = (const float*)d_in[1];
    const float* value_bank = (const float*)d_in[2];
    const int*   bank_mask  = (const int*)  d_in[3];
    const float* Wq = (const float*)d_in[4];
    const float* bq = (const float*)d_in[5];
    const float* Wk = (const float*)d_in[6];
    const float* bk = (const float*)d_in[7];
    const float* Wv = (const float*)d_in[8];
    const float* bv = (const float*)d_in[9];
    const float* Wo = (const float*)d_in[10];
    const float* bo = (const float*)d_in[11];
    const float* gq = (const float*)d_in[12];
    const float* betaq = (const float*)d_in[13];
    const float* gkv = (const float*)d_in[14];
    const float* betakv = (const float*)d_in[15];
    float* out = (float*)d_out;

    __half *Xq, *Xk, *Xv, *Qb, *Kb, *Vb, *Pool;
    float *Oacc, *ML;
    cudaGetSymbolAddress((void**)&Xq,  g_Xq);
    cudaGetSymbolAddress((void**)&Xk,  g_Xk);
    cudaGetSymbolAddress((void**)&Xv,  g_Xv);
    cudaGetSymbolAddress((void**)&Qb,  g_Qb);
    cudaGetSymbolAddress((void**)&Kb,  g_Kb);
    cudaGetSymbolAddress((void**)&Vb,  g_Vb);
    cudaGetSymbolAddress((void**)&Oacc, g_Oacc);
    cudaGetSymbolAddress((void**)&ML,  g_ML);
    cudaGetSymbolAddress((void**)&Pool, g_Pool);

    cudaFuncSetAttribute(attn_f16,
                         cudaFuncAttributeMaxDynamicSharedMemorySize, ATTN_SMEM);

    // 1. Fused LayerNorms (half outputs)
    ln3_kernel<<<MQ + 2 * S_, 256>>>(target, Xq, gq, betaq,
                                     key_bank, value_bank, Xk, Xv, gkv, betakv);

    // 2. Q/K/V projections (half outputs)
    gemm3_f16<<<dim3(D_ / 128, 16, 3), 256>>>(
        Xq, Wq, bq, Qb, MQ,
        Xk, Wk, bk, Kb, S_,
        Xv, Wv, bv, Vb, S_, 1);

    // 3. Attention: fp16 mma, split-KV x3, one wave
    attn_f16<<<dim3(MQ / AQT, H_, NSPLIT), 256, ATTN_SMEM>>>(
        Qb, Kb, Vb, bank_mask, Oacc, ML);

    // 4. Combine + mean-pool (half output)
    combine_pool_kernel<<<(BLn * D_ + 255) / 256, 256>>>(Oacc, ML, Pool);

    // 5. Output projection (fp32 out)
    gemm3_f16<<<dim3(D_ / 128, 2, 1), 256>>>(
        Pool, Wo, bo, out, BLn,
        Pool, Wo, bo, out, BLn,
        Pool, Wo, bo, out, BLn, 0);
}